// round 8
// baseline (speedup 1.0000x reference)
#include <cuda_runtime.h>

#define BB 4
#define CC 64
#define HH 256
#define WW 256
#define HWN 65536
#define HO 130
#define NCHUNK 32

typedef unsigned long long ull;

// ---------------- scratch (device globals; no allocations) ----------------
__device__ float g_qrgb[BB*CC*HWN];
__device__ float g_s  [4][BB*CC*HO*HO];
__device__ float g_cvt[BB*2*CC*HWN];         // conv tmp; later reused for m = (A1 v_r)*(A2 v_d)
__device__ float g_kvr[BB*2*CC*HWN];
__device__ float g_kvd[BB*2*CC*HWN];
__device__ float g_part[2][32][NCHUNK][80];
__device__ float g_attn[2][32][64];

// db3 filters
__constant__ float c_DEC_LO[6] = { 0.035226291882100656f, -0.08544127388224149f, -0.13501102001039084f,
                                   0.4598775021193313f,    0.8068915093133388f,   0.3326705529509569f };
__constant__ float c_DEC_HI[6] = {-0.3326705529509569f,    0.8068915093133388f,  -0.4598775021193313f,
                                  -0.13501102001039084f,   0.08544127388224149f,  0.035226291882100656f };
__constant__ float c_REC_LO[6] = { 0.3326705529509569f,    0.8068915093133388f,   0.4598775021193313f,
                                  -0.13501102001039084f,  -0.08544127388224149f,  0.035226291882100656f };
__constant__ float c_REC_HI[6] = { 0.035226291882100656f,  0.08544127388224149f, -0.13501102001039084f,
                                  -0.4598775021193313f,    0.8068915093133388f,  -0.3326705529509569f };

// ---------------- packed f32x2 helpers ----------------
__device__ __forceinline__ ull pk(float lo, float hi) {
    ull r;
    asm("mov.b64 %0, {%1, %2};" : "=l"(r) : "r"(__float_as_uint(lo)), "r"(__float_as_uint(hi)));
    return r;
}
__device__ __forceinline__ void upk(float& lo, float& hi, ull v) {
    unsigned a, b;
    asm("mov.b64 {%0, %1}, %2;" : "=r"(a), "=r"(b) : "l"(v));
    lo = __uint_as_float(a); hi = __uint_as_float(b);
}
__device__ __forceinline__ void ffma2(ull& d, ull a, ull b) {
    asm("fma.rn.f32x2 %0, %1, %2, %0;" : "+l"(d) : "l"(a), "l"(b));
}
__device__ __forceinline__ ull fmul2(ull a, ull b) {
    ull r; asm("mul.rn.f32x2 %0, %1, %2;" : "=l"(r) : "l"(a), "l"(b)); return r;
}

// ================= fused DWT (rows+cols): rgb -> 4 subbands =================
__global__ __launch_bounds__(256) void mfe_front_k(const float* __restrict__ x) {
    __shared__ float sLo[36*130], sHi[36*130];
    int bc = blockIdx.y;
    int i0 = blockIdx.x * 16;
    int iCnt = min(16, HO - i0);
    int rbase = max(0, 2*i0 - 4);
    int rend  = min(HH-1, 2*(i0 + iCnt - 1) + 1);
    int nR = rend - rbase + 1;
    const float* plane = x + ((size_t)bc << 16);

    for (int idx = threadIdx.x; idx < nR*130; idx += 256) {
        int rl = idx / 130, j = idx - rl*130;
        const float* row = plane + ((rbase + rl) << 8);
        float lo = 0.f, hi = 0.f;
        int base = 2*j - 4;
        #pragma unroll
        for (int s = 0; s < 6; s++) {
            int col = base + s;
            if (col >= 0 && col < WW) {
                float v = row[col];
                lo += v * c_REC_LO[s];
                hi += v * c_REC_HI[s];
            }
        }
        sLo[idx] = lo; sHi[idx] = hi;
    }
    __syncthreads();

    size_t obase = (size_t)bc * (HO*HO);
    for (int idx = threadIdx.x; idx < iCnt*130; idx += 256) {
        int il = idx / 130, xc = idx - il*130;
        int i = i0 + il;
        float ll=0.f, lh=0.f, hl=0.f, hh=0.f;
        int rb = 2*i - 4;
        #pragma unroll
        for (int t = 0; t < 6; t++) {
            int r = rb + t;
            if (r >= 0 && r < HH) {
                int rl = r - rbase;
                float vl = sLo[rl*130 + xc], vh = sHi[rl*130 + xc];
                ll += vl*c_REC_LO[t]; lh += vl*c_REC_HI[t];
                hl += vh*c_REC_LO[t]; hh += vh*c_REC_HI[t];
            }
        }
        size_t o = obase + (size_t)i*HO + xc;
        g_s[0][o]=ll; g_s[1][o]=lh; g_s[2][o]=hl; g_s[3][o]=hh;
    }
}

// ======= fused dw3(subbands) + IDWT(cols+rows): 4 subbands -> qrgb =======
__global__ __launch_bounds__(256) void mfe_back_k(const float* __restrict__ w1, const float* __restrict__ w5,
                                                  const float* __restrict__ w7, const float* __restrict__ w9) {
    extern __shared__ float sdyn[];
    float* sRaw  = sdyn;
    float* sPost = sdyn + 10400;
    __shared__ float sW[36];

    int bc = blockIdx.y;
    int c  = bc & 63;
    int m0 = blockIdx.x * 32;
    int jp0 = m0 >> 1;
    int jr0 = max(0, jp0 - 1);
    int jr1 = min(HO-1, jp0 + 18);
    int nJr = jr1 - jr0 + 1;

    if (threadIdx.x < 36) {
        int s = threadIdx.x / 9, k = threadIdx.x - s*9;
        const float* wp = (s==0) ? w1 : (s==1) ? w5 : (s==2) ? w7 : w9;
        sW[threadIdx.x] = wp[c*9 + k];
    }

    size_t sbase = (size_t)bc * (HO*HO);
    int nElems = 4*nJr*130;
    for (int idx = threadIdx.x; idx < nElems; idx += 256) {
        int s = idx / (nJr*130);
        int rem = idx - s*nJr*130;
        int rl = rem / 130, xc = rem - rl*130;
        sRaw[s*(20*130) + rl*130 + xc] = g_s[s][sbase + (size_t)(jr0+rl)*HO + xc];
    }
    __syncthreads();

    for (int idx = threadIdx.x; idx < 4*18*130; idx += 256) {
        int s = idx / (18*130);
        int rem = idx - s*(18*130);
        int pl = rem / 130, xc = rem - pl*130;
        int jglob = jp0 + pl;
        const float* wr = sW + s*9;
        const float* rb = sRaw + s*(20*130);
        float acc = 0.f;
        #pragma unroll
        for (int dy = -1; dy <= 1; dy++) {
            int jn = jglob + dy;
            if (jn < 0 || jn >= HO) continue;
            int rl = jn - jr0;
            #pragma unroll
            for (int dx = -1; dx <= 1; dx++) {
                int xn = xc + dx;
                if (xn < 0 || xn >= HO) continue;
                acc += rb[rl*130 + xn] * wr[(dy+1)*3 + (dx+1)];
            }
        }
        sPost[idx] = acc;
    }
    __syncthreads();

    float* sL2 = sRaw;
    float* sH2 = sRaw + 4160;
    for (int idx = threadIdx.x; idx < 32*130; idx += 256) {
        int ml = idx / 130, xc = idx - ml*130;
        int m = m0 + ml;
        int i0f = (m & 1) ? 0 : 1;
        int jl = (m >> 1) - jp0;
        float lo = 0.f, hi = 0.f;
        #pragma unroll
        for (int t = 0; t < 3; t++) {
            int fi = i0f + 2*t;
            int pr = jl + t;
            float a0 = sPost[0*(18*130) + pr*130 + xc];
            float a1 = sPost[1*(18*130) + pr*130 + xc];
            float a2 = sPost[2*(18*130) + pr*130 + xc];
            float a3 = sPost[3*(18*130) + pr*130 + xc];
            lo += a0*c_DEC_LO[fi] + a1*c_DEC_HI[fi];
            hi += a2*c_DEC_LO[fi] + a3*c_DEC_HI[fi];
        }
        sL2[idx] = lo; sH2[idx] = hi;
    }
    __syncthreads();

    float* oplane = g_qrgb + ((size_t)bc << 16);
    for (int idx = threadIdx.x; idx < 32*256; idx += 256) {
        int ml = idx >> 8, w = idx & 255;
        int i0f = (w & 1) ? 0 : 1;
        int j0w = w >> 1;
        const float* lrow = sL2 + ml*130;
        const float* hrow = sH2 + ml*130;
        float acc = 0.f;
        #pragma unroll
        for (int t = 0; t < 3; t++) {
            int fi = i0f + 2*t;
            acc += lrow[j0w+t]*c_DEC_LO[fi] + hrow[j0w+t]*c_DEC_HI[fi];
        }
        oplane[((m0 + ml) << 8) + w] = acc;
    }
}

// ======== 1x1 conv 64->128: transposed undup weights, LDS.128, f32x2 ========
__global__ __launch_bounds__(256) void conv1x1_k(const float* __restrict__ in,
                                                 const float* __restrict__ w,
                                                 float* __restrict__ out) {
    __shared__ float swT[64*128];    // [c][o], 32 KB, unduplicated
    for (int i = threadIdx.x; i < 8192; i += 256) {
        int o = i & 127, c = i >> 7;
        swT[i] = w[o*64 + c];
    }
    __syncthreads();
    int b = blockIdx.y;
    int pb = (blockIdx.x*256 + threadIdx.x)*4;
    const float* ib = in  + (size_t)b*CC*HWN + pb;
    float*       ob = out + (size_t)b*(2*CC)*HWN + pb;

    #pragma unroll 1
    for (int ot = 0; ot < 8; ot++) {
        ull a0[16], a1[16];
        #pragma unroll
        for (int o = 0; o < 16; o++) { a0[o] = 0ULL; a1[o] = 0ULL; }
        #pragma unroll 2
        for (int c = 0; c < 64; c++) {
            float4 x = *(const float4*)(ib + (size_t)c*HWN);
            ull x01 = pk(x.x, x.y), x23 = pk(x.z, x.w);
            const float4* wr = (const float4*)(swT + (c << 7) + (ot << 4));
            float4 wa = wr[0], wb = wr[1], wc4 = wr[2], wd = wr[3];
            float wf[16] = {wa.x,wa.y,wa.z,wa.w, wb.x,wb.y,wb.z,wb.w,
                            wc4.x,wc4.y,wc4.z,wc4.w, wd.x,wd.y,wd.z,wd.w};
            #pragma unroll
            for (int o = 0; o < 16; o++) {
                ull wv = pk(wf[o], wf[o]);
                ffma2(a0[o], wv, x01);
                ffma2(a1[o], wv, x23);
            }
        }
        #pragma unroll
        for (int o = 0; o < 16; o++) {
            float4 r;
            upk(r.x, r.y, a0[o]);
            upk(r.z, r.w, a1[o]);
            *(float4*)(ob + (size_t)(ot*16 + o)*HWN) = r;
        }
    }
}

// ======== depthwise 3x3, C=128: smem row strips, 16 px/thread ========
__global__ __launch_bounds__(256) void dw3_big_k(const float* __restrict__ in,
                                                 const float* __restrict__ wt,
                                                 float* __restrict__ out) {
    __shared__ float st[18][264];     // rows y0-1..y0+16; data at cols [4..259]; zeros at [3],[260]
    int bc = blockIdx.y;              // 0..BB*128-1
    int c  = bc & 127;
    int y0 = blockIdx.x * 16;
    const float* plane = in + ((size_t)bc << 16);

    float wreg[9];
    #pragma unroll
    for (int k = 0; k < 9; k++) wreg[k] = wt[c*9 + k];

    // zero edge columns
    if (threadIdx.x < 36) {
        int r = threadIdx.x >> 1;
        st[r][(threadIdx.x & 1) ? 260 : 3] = 0.f;
    }
    // stage 18 rows (zero rows outside [0,255])
    for (int i = threadIdx.x; i < 18*64; i += 256) {
        int r = i >> 6, q = i & 63;
        int y = y0 - 1 + r;
        float4 v = make_float4(0.f, 0.f, 0.f, 0.f);
        if (y >= 0 && y < HH) v = *(const float4*)(plane + (y << 8) + (q << 2));
        *(float4*)&st[r][4 + (q << 2)] = v;
    }
    __syncthreads();

    float* oplane = out + ((size_t)bc << 16);
    #pragma unroll
    for (int g = 0; g < 4; g++) {
        int idx = g*256 + threadIdx.x;       // 0..1023
        int row = idx >> 6;                  // 0..15
        int q   = idx & 63;
        int x0  = q << 2;
        float acc0 = 0.f, acc1 = 0.f, acc2 = 0.f, acc3 = 0.f;
        #pragma unroll
        for (int dr = 0; dr < 3; dr++) {
            const float* rw = &st[row + dr][4 + x0];
            float4 v = *(const float4*)rw;
            float L = rw[-1], R = rw[4];
            float w0 = wreg[dr*3], w1 = wreg[dr*3+1], w2 = wreg[dr*3+2];
            acc0 += w0*L   + w1*v.x + w2*v.y;
            acc1 += w0*v.x + w1*v.y + w2*v.z;
            acc2 += w0*v.y + w1*v.z + w2*v.w;
            acc3 += w0*v.z + w1*v.w + w2*R;
        }
        *(float4*)(oplane + ((y0 + row) << 8) + x0) = make_float4(acc0, acc1, acc2, acc3);
    }
}

// ---------- fused Gram reduction: q read once, both modalities ----------
__global__ __launch_bounds__(256, 1) void reduce_qk2_k(const float* __restrict__ q,
                                                       const float* __restrict__ kvr,
                                                       const float* __restrict__ kvd) {
    int chunk = blockIdx.x;
    int bh    = blockIdx.y;
    int b = bh >> 3, h = bh & 7;
    size_t qoff = ((size_t)b*64  + h*8)*HWN;
    size_t koff = ((size_t)b*128 + h*8)*HWN;

    float accr[64], accd[64], qn[8], knr[8], knd[8];
    #pragma unroll
    for (int i = 0; i < 64; i++) { accr[i] = 0.f; accd[i] = 0.f; }
    #pragma unroll
    for (int i = 0; i < 8; i++) { qn[i] = 0.f; knr[i] = 0.f; knd[i] = 0.f; }

    const int CS4 = HWN / NCHUNK / 4;
    int start = chunk * CS4;
    for (int it = threadIdx.x; it < CS4; it += blockDim.x) {
        int idx = start + it;
        float4 qv[8];
        #pragma unroll
        for (int c = 0; c < 8; c++) {
            qv[c] = ((const float4*)(q + qoff + (size_t)c*HWN))[idx];
            qn[c] += qv[c].x*qv[c].x + qv[c].y*qv[c].y + qv[c].z*qv[c].z + qv[c].w*qv[c].w;
        }
        #pragma unroll
        for (int d = 0; d < 8; d++) {
            float4 k4 = ((const float4*)(kvr + koff + (size_t)d*HWN))[idx];
            knr[d] += k4.x*k4.x + k4.y*k4.y + k4.z*k4.z + k4.w*k4.w;
            #pragma unroll
            for (int c = 0; c < 8; c++)
                accr[d*8+c] += qv[c].x*k4.x + qv[c].y*k4.y + qv[c].z*k4.z + qv[c].w*k4.w;
        }
        #pragma unroll
        for (int d = 0; d < 8; d++) {
            float4 k4 = ((const float4*)(kvd + koff + (size_t)d*HWN))[idx];
            knd[d] += k4.x*k4.x + k4.y*k4.y + k4.z*k4.z + k4.w*k4.w;
            #pragma unroll
            for (int c = 0; c < 8; c++)
                accd[d*8+c] += qv[c].x*k4.x + qv[c].y*k4.y + qv[c].z*k4.z + qv[c].w*k4.w;
        }
    }

    __shared__ float sm[8][152];
    int lane = threadIdx.x & 31, warp = threadIdx.x >> 5;
    #pragma unroll
    for (int v = 0; v < 64; v++) {
        float r = accr[v];
        for (int s = 16; s > 0; s >>= 1) r += __shfl_down_sync(0xffffffffu, r, s);
        if (lane == 0) sm[warp][v] = r;
        float r2 = accd[v];
        for (int s = 16; s > 0; s >>= 1) r2 += __shfl_down_sync(0xffffffffu, r2, s);
        if (lane == 0) sm[warp][80+v] = r2;
    }
    #pragma unroll
    for (int v = 0; v < 8; v++) {
        float r = qn[v];
        for (int s = 16; s > 0; s >>= 1) r += __shfl_down_sync(0xffffffffu, r, s);
        if (lane == 0) sm[warp][64+v] = r;
        float r2 = knr[v];
        for (int s = 16; s > 0; s >>= 1) r2 += __shfl_down_sync(0xffffffffu, r2, s);
        if (lane == 0) sm[warp][72+v] = r2;
        float r3 = knd[v];
        for (int s = 16; s > 0; s >>= 1) r3 += __shfl_down_sync(0xffffffffu, r3, s);
        if (lane == 0) sm[warp][144+v] = r3;
    }
    __syncthreads();
    if (threadIdx.x < 160) {
        int which = threadIdx.x / 80;
        int t = threadIdx.x - which*80;
        int col;
        if (which == 0) col = t;
        else            col = (t < 64) ? 80 + t : (t < 72 ? t : 72 + t);
        float s = 0.f;
        #pragma unroll
        for (int wg = 0; wg < 8; wg++) s += sm[wg][col];
        g_part[which][bh][chunk][t] = s;
    }
}

// ---------------- finish reduction + softmax ----------------
__global__ void attn_k(const float* __restrict__ temp) {
    int which = blockIdx.x >> 5;
    int bh    = blockIdx.x & 31;
    int h     = bh & 7;
    __shared__ float sm[80];
    if (threadIdx.x < 80) {
        float s = 0.f;
        #pragma unroll
        for (int ch = 0; ch < NCHUNK; ch++) s += g_part[which][bh][ch][threadIdx.x];
        sm[threadIdx.x] = s;
    }
    __syncthreads();
    if (threadIdx.x < 8) {
        int c = threadIdx.x;
        float t  = temp[h];
        float nq = fmaxf(sqrtf(sm[64+c]), 1e-12f);
        float srow[8];
        #pragma unroll
        for (int d = 0; d < 8; d++) {
            float nk = fmaxf(sqrtf(sm[72+d]), 1e-12f);
            float s = sm[d*8+c] / nk;
            if (which == 0) s /= nq;
            srow[d] = s * t;
        }
        float mx = srow[0];
        #pragma unroll
        for (int d = 1; d < 8; d++) mx = fmaxf(mx, srow[d]);
        float sum = 0.f;
        #pragma unroll
        for (int d = 0; d < 8; d++) { srow[d] = __expf(srow[d]-mx); sum += srow[d]; }
        float inv = 1.f / sum;
        #pragma unroll
        for (int d = 0; d < 8; d++) g_attn[which][bh][c*8+d] = srow[d]*inv;
    }
}

// ======== mix: m[c] = (attn1·v_r)[c] * (attn2·v_d)[c], 4 px/thread ========
__global__ __launch_bounds__(256) void mix_k() {
    __shared__ float sA1t[512], sA2t[512];   // transposed [h][d][c], unduplicated
    int b = blockIdx.y;
    for (int i = threadIdx.x; i < 512; i += 256) {
        int h = i >> 6, d = (i >> 3) & 7, c = i & 7;
        sA1t[i] = g_attn[0][b*8 + h][c*8 + d];
        sA2t[i] = g_attn[1][b*8 + h][c*8 + d];
    }
    __syncthreads();

    int n = (blockIdx.x*256 + threadIdx.x)*4;
    const float* vr = g_kvr + ((size_t)b*128 + 64)*HWN + n;
    const float* vd = g_kvd + ((size_t)b*128 + 64)*HWN + n;
    float* mb = g_cvt + (size_t)b*64*HWN + n;

    #pragma unroll 1
    for (int h = 0; h < 8; h++) {
        ull os0[8], os1[8], oc0[8], oc1[8];
        #pragma unroll
        for (int c = 0; c < 8; c++) { os0[c]=0ULL; os1[c]=0ULL; oc0[c]=0ULL; oc1[c]=0ULL; }
        #pragma unroll
        for (int d = 0; d < 8; d++) {
            float4 r4 = *(const float4*)(vr + (size_t)(h*8+d)*HWN);
            float4 d4 = *(const float4*)(vd + (size_t)(h*8+d)*HWN);
            ull rr0 = pk(r4.x, r4.y), rr1 = pk(r4.z, r4.w);
            ull dd0 = pk(d4.x, d4.y), dd1 = pk(d4.z, d4.w);
            const float4* a1p = (const float4*)(sA1t + h*64 + d*8);
            const float4* a2p = (const float4*)(sA2t + h*64 + d*8);
            float4 a1a = a1p[0], a1b = a1p[1];
            float4 a2a = a2p[0], a2b = a2p[1];
            float a1f[8] = {a1a.x,a1a.y,a1a.z,a1a.w, a1b.x,a1b.y,a1b.z,a1b.w};
            float a2f[8] = {a2a.x,a2a.y,a2a.z,a2a.w, a2b.x,a2b.y,a2b.z,a2b.w};
            #pragma unroll
            for (int c = 0; c < 8; c++) {
                ull w1 = pk(a1f[c], a1f[c]);
                ffma2(os0[c], w1, rr0);
                ffma2(os1[c], w1, rr1);
                ull w2 = pk(a2f[c], a2f[c]);
                ffma2(oc0[c], w2, dd0);
                ffma2(oc1[c], w2, dd1);
            }
        }
        #pragma unroll
        for (int c = 0; c < 8; c++) {
            ull m0 = fmul2(os0[c], oc0[c]);
            ull m1 = fmul2(os1[c], oc1[c]);
            float4 r;
            upk(r.x, r.y, m0);
            upk(r.z, r.w, m1);
            *(float4*)(mb + (size_t)(h*8+c)*HWN) = r;
        }
    }
}

// ======== proj: out = wproj (64x64) * m, same structure as conv1x1 ========
__global__ __launch_bounds__(256) void proj_k(const float* __restrict__ w,
                                              float* __restrict__ out) {
    __shared__ float swT[64*64];     // [c][o], 16 KB
    for (int i = threadIdx.x; i < 4096; i += 256) {
        int o = i & 63, c = i >> 6;
        swT[i] = w[o*64 + c];
    }
    __syncthreads();
    int b = blockIdx.y;
    int pb = (blockIdx.x*256 + threadIdx.x)*4;
    const float* ib = g_cvt + (size_t)b*64*HWN + pb;
    float*       ob = out   + (size_t)b*64*HWN + pb;

    #pragma unroll 1
    for (int ot = 0; ot < 4; ot++) {
        ull a0[16], a1[16];
        #pragma unroll
        for (int o = 0; o < 16; o++) { a0[o] = 0ULL; a1[o] = 0ULL; }
        #pragma unroll 2
        for (int c = 0; c < 64; c++) {
            float4 x = *(const float4*)(ib + (size_t)c*HWN);
            ull x01 = pk(x.x, x.y), x23 = pk(x.z, x.w);
            const float4* wr = (const float4*)(swT + (c << 6) + (ot << 4));
            float4 wa = wr[0], wb = wr[1], wc4 = wr[2], wd = wr[3];
            float wf[16] = {wa.x,wa.y,wa.z,wa.w, wb.x,wb.y,wb.z,wb.w,
                            wc4.x,wc4.y,wc4.z,wc4.w, wd.x,wd.y,wd.z,wd.w};
            #pragma unroll
            for (int o = 0; o < 16; o++) {
                ull wv = pk(wf[o], wf[o]);
                ffma2(a0[o], wv, x01);
                ffma2(a1[o], wv, x23);
            }
        }
        #pragma unroll
        for (int o = 0; o < 16; o++) {
            float4 r;
            upk(r.x, r.y, a0[o]);
            upk(r.z, r.w, a1[o]);
            *(float4*)(ob + (size_t)(ot*16 + o)*HWN) = r;
        }
    }
}

// ---------------- host launch ----------------
extern "C" void kernel_launch(void* const* d_in, const int* in_sizes, int n_in,
                              void* d_out, int out_size) {
    const float* rgb   = (const float*)d_in[0];
    const float* depth = (const float*)d_in[1];
    const float* temp  = (const float*)d_in[2];
    const float* wqr   = (const float*)d_in[3];
    const float* wqd   = (const float*)d_in[4];
    const float* wqc   = (const float*)d_in[5];
    const float* w1    = (const float*)d_in[6];
    const float* w5    = (const float*)d_in[7];
    const float* w7    = (const float*)d_in[8];
    const float* w9    = (const float*)d_in[9];
    const float* wproj = (const float*)d_in[10];
    float* out = (float*)d_out;

    void* p;
    cudaGetSymbolAddress(&p, g_qrgb); float* qrg = (float*)p;
    cudaGetSymbolAddress(&p, g_cvt);  float* cvt = (float*)p;
    cudaGetSymbolAddress(&p, g_kvr);  float* kvr = (float*)p;
    cudaGetSymbolAddress(&p, g_kvd);  float* kvd = (float*)p;

    const int T = 256;
    const int MFE_BACK_SMEM = (10400 + 9360) * 4;   // 79040 B
    cudaFuncSetAttribute(mfe_back_k, cudaFuncAttributeMaxDynamicSharedMemorySize, MFE_BACK_SMEM);

    // ---- MFE (2 fused kernels) ----
    dim3 fgk(9, BB*CC);
    mfe_front_k<<<fgk, T>>>(rgb);
    dim3 bgk(8, BB*CC);
    mfe_back_k<<<bgk, T, MFE_BACK_SMEM>>>(w1, w5, w7, w9);

    // ---- kv paths ----
    dim3 cg(HWN/(T*4), BB);
    dim3 dg(16, BB*128);                 // 16 strips of 16 rows x 512 planes
    conv1x1_k<<<cg, T>>>(rgb, wqr, cvt);
    dw3_big_k<<<dg, T>>>(cvt, wqc, kvr);
    conv1x1_k<<<cg, T>>>(depth, wqd, cvt);
    dw3_big_k<<<dg, T>>>(cvt, wqc, kvd);

    // ---- attention statistics ----
    dim3 rg(NCHUNK, 32);
    reduce_qk2_k<<<rg, T>>>(qrg, kvr, kvd);
    attn_k<<<64, 128>>>(temp);

    // ---- epilogue: mix then proj ----
    dim3 mg(HWN/(T*4), BB);
    mix_k<<<mg, T>>>();
    proj_k<<<mg, T>>>(wproj, out);
}

// round 9
// speedup vs baseline: 1.2826x; 1.2826x over previous
#include <cuda_runtime.h>

#define BB 4
#define CC 64
#define HH 256
#define WW 256
#define HWN 65536
#define HO 130
#define NCHUNK 32

typedef unsigned long long ull;

// ---------------- scratch (device globals; no allocations) ----------------
__device__ float g_qrgb[BB*CC*HWN];
__device__ float g_s  [4][BB*CC*HO*HO];
__device__ float g_cvt0[BB*2*CC*HWN];
__device__ float g_cvt1[BB*2*CC*HWN];
__device__ float g_kvr[BB*2*CC*HWN];
__device__ float g_kvd[BB*2*CC*HWN];
__device__ float g_part[2][32][NCHUNK][80];
__device__ float g_attn[2][32][64];

// db3 filters
__constant__ float c_DEC_LO[6] = { 0.035226291882100656f, -0.08544127388224149f, -0.13501102001039084f,
                                   0.4598775021193313f,    0.8068915093133388f,   0.3326705529509569f };
__constant__ float c_DEC_HI[6] = {-0.3326705529509569f,    0.8068915093133388f,  -0.4598775021193313f,
                                  -0.13501102001039084f,   0.08544127388224149f,  0.035226291882100656f };
__constant__ float c_REC_LO[6] = { 0.3326705529509569f,    0.8068915093133388f,   0.4598775021193313f,
                                  -0.13501102001039084f,  -0.08544127388224149f,  0.035226291882100656f };
__constant__ float c_REC_HI[6] = { 0.035226291882100656f,  0.08544127388224149f, -0.13501102001039084f,
                                  -0.4598775021193313f,    0.8068915093133388f,  -0.3326705529509569f };

// ---------------- packed f32x2 helpers ----------------
__device__ __forceinline__ ull pk(float lo, float hi) {
    ull r;
    asm("mov.b64 %0, {%1, %2};" : "=l"(r) : "r"(__float_as_uint(lo)), "r"(__float_as_uint(hi)));
    return r;
}
__device__ __forceinline__ void upk(float& lo, float& hi, ull v) {
    unsigned a, b;
    asm("mov.b64 {%0, %1}, %2;" : "=r"(a), "=r"(b) : "l"(v));
    lo = __uint_as_float(a); hi = __uint_as_float(b);
}
__device__ __forceinline__ void ffma2(ull& d, ull a, ull b) {
    asm("fma.rn.f32x2 %0, %1, %2, %0;" : "+l"(d) : "l"(a), "l"(b));
}
__device__ __forceinline__ ull fmul2(ull a, ull b) {
    ull r; asm("mul.rn.f32x2 %0, %1, %2;" : "=l"(r) : "l"(a), "l"(b)); return r;
}

// ================= fused DWT (rows+cols): rgb -> 4 subbands =================
__global__ __launch_bounds__(256) void mfe_front_k(const float* __restrict__ x) {
    __shared__ float sLo[36*130], sHi[36*130];
    int bc = blockIdx.y;
    int i0 = blockIdx.x * 16;
    int iCnt = min(16, HO - i0);
    int rbase = max(0, 2*i0 - 4);
    int rend  = min(HH-1, 2*(i0 + iCnt - 1) + 1);
    int nR = rend - rbase + 1;
    const float* plane = x + ((size_t)bc << 16);

    for (int idx = threadIdx.x; idx < nR*130; idx += 256) {
        int rl = idx / 130, j = idx - rl*130;
        const float* row = plane + ((rbase + rl) << 8);
        float lo = 0.f, hi = 0.f;
        int base = 2*j - 4;
        #pragma unroll
        for (int s = 0; s < 6; s++) {
            int col = base + s;
            if (col >= 0 && col < WW) {
                float v = row[col];
                lo += v * c_REC_LO[s];
                hi += v * c_REC_HI[s];
            }
        }
        sLo[idx] = lo; sHi[idx] = hi;
    }
    __syncthreads();

    size_t obase = (size_t)bc * (HO*HO);
    for (int idx = threadIdx.x; idx < iCnt*130; idx += 256) {
        int il = idx / 130, xc = idx - il*130;
        int i = i0 + il;
        float ll=0.f, lh=0.f, hl=0.f, hh=0.f;
        int rb = 2*i - 4;
        #pragma unroll
        for (int t = 0; t < 6; t++) {
            int r = rb + t;
            if (r >= 0 && r < HH) {
                int rl = r - rbase;
                float vl = sLo[rl*130 + xc], vh = sHi[rl*130 + xc];
                ll += vl*c_REC_LO[t]; lh += vl*c_REC_HI[t];
                hl += vh*c_REC_LO[t]; hh += vh*c_REC_HI[t];
            }
        }
        size_t o = obase + (size_t)i*HO + xc;
        g_s[0][o]=ll; g_s[1][o]=lh; g_s[2][o]=hl; g_s[3][o]=hh;
    }
}

// ======= fused dw3(subbands) + IDWT(cols+rows): 4 subbands -> qrgb =======
__global__ __launch_bounds__(256) void mfe_back_k(const float* __restrict__ w1, const float* __restrict__ w5,
                                                  const float* __restrict__ w7, const float* __restrict__ w9) {
    extern __shared__ float sdyn[];
    float* sRaw  = sdyn;
    float* sPost = sdyn + 10400;
    __shared__ float sW[36];

    int bc = blockIdx.y;
    int c  = bc & 63;
    int m0 = blockIdx.x * 32;
    int jp0 = m0 >> 1;
    int jr0 = max(0, jp0 - 1);
    int jr1 = min(HO-1, jp0 + 18);
    int nJr = jr1 - jr0 + 1;

    if (threadIdx.x < 36) {
        int s = threadIdx.x / 9, k = threadIdx.x - s*9;
        const float* wp = (s==0) ? w1 : (s==1) ? w5 : (s==2) ? w7 : w9;
        sW[threadIdx.x] = wp[c*9 + k];
    }

    size_t sbase = (size_t)bc * (HO*HO);
    int nElems = 4*nJr*130;
    for (int idx = threadIdx.x; idx < nElems; idx += 256) {
        int s = idx / (nJr*130);
        int rem = idx - s*nJr*130;
        int rl = rem / 130, xc = rem - rl*130;
        sRaw[s*(20*130) + rl*130 + xc] = g_s[s][sbase + (size_t)(jr0+rl)*HO + xc];
    }
    __syncthreads();

    for (int idx = threadIdx.x; idx < 4*18*130; idx += 256) {
        int s = idx / (18*130);
        int rem = idx - s*(18*130);
        int pl = rem / 130, xc = rem - pl*130;
        int jglob = jp0 + pl;
        const float* wr = sW + s*9;
        const float* rb = sRaw + s*(20*130);
        float acc = 0.f;
        #pragma unroll
        for (int dy = -1; dy <= 1; dy++) {
            int jn = jglob + dy;
            if (jn < 0 || jn >= HO) continue;
            int rl = jn - jr0;
            #pragma unroll
            for (int dx = -1; dx <= 1; dx++) {
                int xn = xc + dx;
                if (xn < 0 || xn >= HO) continue;
                acc += rb[rl*130 + xn] * wr[(dy+1)*3 + (dx+1)];
            }
        }
        sPost[idx] = acc;
    }
    __syncthreads();

    float* sL2 = sRaw;
    float* sH2 = sRaw + 4160;
    for (int idx = threadIdx.x; idx < 32*130; idx += 256) {
        int ml = idx / 130, xc = idx - ml*130;
        int m = m0 + ml;
        int i0f = (m & 1) ? 0 : 1;
        int jl = (m >> 1) - jp0;
        float lo = 0.f, hi = 0.f;
        #pragma unroll
        for (int t = 0; t < 3; t++) {
            int fi = i0f + 2*t;
            int pr = jl + t;
            float a0 = sPost[0*(18*130) + pr*130 + xc];
            float a1 = sPost[1*(18*130) + pr*130 + xc];
            float a2 = sPost[2*(18*130) + pr*130 + xc];
            float a3 = sPost[3*(18*130) + pr*130 + xc];
            lo += a0*c_DEC_LO[fi] + a1*c_DEC_HI[fi];
            hi += a2*c_DEC_LO[fi] + a3*c_DEC_HI[fi];
        }
        sL2[idx] = lo; sH2[idx] = hi;
    }
    __syncthreads();

    float* oplane = g_qrgb + ((size_t)bc << 16);
    for (int idx = threadIdx.x; idx < 32*256; idx += 256) {
        int ml = idx >> 8, w = idx & 255;
        int i0f = (w & 1) ? 0 : 1;
        int j0w = w >> 1;
        const float* lrow = sL2 + ml*130;
        const float* hrow = sH2 + ml*130;
        float acc = 0.f;
        #pragma unroll
        for (int t = 0; t < 3; t++) {
            int fi = i0f + 2*t;
            acc += lrow[j0w+t]*c_DEC_LO[fi] + hrow[j0w+t]*c_DEC_HI[fi];
        }
        oplane[((m0 + ml) << 8) + w] = acc;
    }
}

// ======== 1x1 conv 64->128 (R7 version: dup weights, broadcast LDS) ========
// grid.z: 0 = rgb->cvt0, 1 = depth->cvt1
__global__ __launch_bounds__(256) void conv1x1_duo_k(const float* __restrict__ rgb,
                                                     const float* __restrict__ depth,
                                                     const float* __restrict__ wqr,
                                                     const float* __restrict__ wqd) {
    __shared__ ull sw2[64*64];
    int mod = blockIdx.z;
    const float* in = mod ? depth : rgb;
    const float* w  = mod ? wqd   : wqr;
    float* out = mod ? g_cvt1 : g_cvt0;
    int b = blockIdx.y;
    int pb = (blockIdx.x*256 + threadIdx.x)*4;
    const float* ib = in  + (size_t)b*CC*HWN + pb;
    float*       ob = out + (size_t)b*(2*CC)*HWN + pb;

    for (int half = 0; half < 2; half++) {
        for (int i = threadIdx.x; i < 4096; i += 256) {
            float wv = w[half*4096 + i];
            sw2[i] = pk(wv, wv);
        }
        __syncthreads();
        #pragma unroll 1
        for (int ot = 0; ot < 4; ot++) {
            ull a0[16], a1[16];
            #pragma unroll
            for (int o = 0; o < 16; o++) { a0[o] = 0ULL; a1[o] = 0ULL; }
            #pragma unroll 4
            for (int c = 0; c < 64; c++) {
                float4 x = *(const float4*)(ib + (size_t)c*HWN);
                ull x01 = pk(x.x, x.y), x23 = pk(x.z, x.w);
                const ull* wr = sw2 + (ot*16)*64 + c;
                #pragma unroll
                for (int o = 0; o < 16; o++) {
                    ull wv = wr[o*64];
                    ffma2(a0[o], wv, x01);
                    ffma2(a1[o], wv, x23);
                }
            }
            #pragma unroll
            for (int o = 0; o < 16; o++) {
                float4 r;
                upk(r.x, r.y, a0[o]);
                upk(r.z, r.w, a1[o]);
                *(float4*)(ob + (size_t)(half*64 + ot*16 + o)*HWN) = r;
            }
        }
        __syncthreads();
    }
}

// ======== depthwise 3x3, shuffle edges, 8 px/thread, rolling rows ========
struct Row8 {
    float4 A, B;
    float pw, nx;
};
__device__ __forceinline__ Row8 load_row8(const float* plane, int y, int lane) {
    Row8 r;
    if (y < 0 || y >= HH) {
        r.A = make_float4(0.f,0.f,0.f,0.f);
        r.B = r.A; r.pw = 0.f; r.nx = 0.f;
        // still participate in shuffles below with zeros
        float pw = __shfl_up_sync(0xffffffffu, 0.f, 1);
        float nx = __shfl_down_sync(0xffffffffu, 0.f, 1);
        (void)pw; (void)nx;
        return r;
    }
    const float* p = plane + (y << 8) + (lane << 3);
    r.A = *(const float4*)p;
    r.B = *(const float4*)(p + 4);
    float pw = __shfl_up_sync(0xffffffffu, r.B.w, 1);
    float nx = __shfl_down_sync(0xffffffffu, r.A.x, 1);
    r.pw = (lane == 0)  ? 0.f : pw;
    r.nx = (lane == 31) ? 0.f : nx;
    return r;
}
__device__ __forceinline__ void acc_row8(float* acc, const Row8& r, float wa, float wb, float wc) {
    acc[0] += wa*r.pw  + wb*r.A.x + wc*r.A.y;
    acc[1] += wa*r.A.x + wb*r.A.y + wc*r.A.z;
    acc[2] += wa*r.A.y + wb*r.A.z + wc*r.A.w;
    acc[3] += wa*r.A.z + wb*r.A.w + wc*r.B.x;
    acc[4] += wa*r.A.w + wb*r.B.x + wc*r.B.y;
    acc[5] += wa*r.B.x + wb*r.B.y + wc*r.B.z;
    acc[6] += wa*r.B.y + wb*r.B.z + wc*r.B.w;
    acc[7] += wa*r.B.z + wb*r.B.w + wc*r.nx;
}

// grid: (4 strips of 64 rows, 512 planes, 2 modalities). warp handles 8 rows.
__global__ __launch_bounds__(256) void dw3_duo_k(const float* __restrict__ wt) {
    int mod = blockIdx.z;
    const float* in = mod ? g_cvt1 : g_cvt0;
    float* out = mod ? g_kvd : g_kvr;
    int bc = blockIdx.y;
    int c  = bc & 127;
    int warp = threadIdx.x >> 5, lane = threadIdx.x & 31;
    int yb = blockIdx.x*64 + warp*8;

    float w[9];
    #pragma unroll
    for (int k = 0; k < 9; k++) w[k] = wt[c*9 + k];

    const float* plane = in  + ((size_t)bc << 16);
    float*      oplane = out + ((size_t)bc << 16);

    Row8 rp = load_row8(plane, yb - 1, lane);
    Row8 rc = load_row8(plane, yb,     lane);
    #pragma unroll
    for (int i = 0; i < 8; i++) {
        Row8 rn = load_row8(plane, yb + i + 1, lane);
        float acc[8];
        #pragma unroll
        for (int k = 0; k < 8; k++) acc[k] = 0.f;
        acc_row8(acc, rp, w[0], w[1], w[2]);
        acc_row8(acc, rc, w[3], w[4], w[5]);
        acc_row8(acc, rn, w[6], w[7], w[8]);
        float* op = oplane + ((yb + i) << 8) + (lane << 3);
        *(float4*)op       = make_float4(acc[0], acc[1], acc[2], acc[3]);
        *(float4*)(op + 4) = make_float4(acc[4], acc[5], acc[6], acc[7]);
        rp = rc; rc = rn;
    }
}

// ---------- fused Gram reduction: q read once, both modalities ----------
__global__ __launch_bounds__(256, 1) void reduce_qk2_k(const float* __restrict__ q,
                                                       const float* __restrict__ kvr,
                                                       const float* __restrict__ kvd) {
    int chunk = blockIdx.x;
    int bh    = blockIdx.y;
    int b = bh >> 3, h = bh & 7;
    size_t qoff = ((size_t)b*64  + h*8)*HWN;
    size_t koff = ((size_t)b*128 + h*8)*HWN;

    float accr[64], accd[64], qn[8], knr[8], knd[8];
    #pragma unroll
    for (int i = 0; i < 64; i++) { accr[i] = 0.f; accd[i] = 0.f; }
    #pragma unroll
    for (int i = 0; i < 8; i++) { qn[i] = 0.f; knr[i] = 0.f; knd[i] = 0.f; }

    const int CS4 = HWN / NCHUNK / 4;
    int start = chunk * CS4;
    for (int it = threadIdx.x; it < CS4; it += blockDim.x) {
        int idx = start + it;
        float4 qv[8];
        #pragma unroll
        for (int c = 0; c < 8; c++) {
            qv[c] = ((const float4*)(q + qoff + (size_t)c*HWN))[idx];
            qn[c] += qv[c].x*qv[c].x + qv[c].y*qv[c].y + qv[c].z*qv[c].z + qv[c].w*qv[c].w;
        }
        #pragma unroll
        for (int d = 0; d < 8; d++) {
            float4 k4 = ((const float4*)(kvr + koff + (size_t)d*HWN))[idx];
            knr[d] += k4.x*k4.x + k4.y*k4.y + k4.z*k4.z + k4.w*k4.w;
            #pragma unroll
            for (int c = 0; c < 8; c++)
                accr[d*8+c] += qv[c].x*k4.x + qv[c].y*k4.y + qv[c].z*k4.z + qv[c].w*k4.w;
        }
        #pragma unroll
        for (int d = 0; d < 8; d++) {
            float4 k4 = ((const float4*)(kvd + koff + (size_t)d*HWN))[idx];
            knd[d] += k4.x*k4.x + k4.y*k4.y + k4.z*k4.z + k4.w*k4.w;
            #pragma unroll
            for (int c = 0; c < 8; c++)
                accd[d*8+c] += qv[c].x*k4.x + qv[c].y*k4.y + qv[c].z*k4.z + qv[c].w*k4.w;
        }
    }

    __shared__ float sm[8][152];
    int lane = threadIdx.x & 31, warp = threadIdx.x >> 5;
    #pragma unroll
    for (int v = 0; v < 64; v++) {
        float r = accr[v];
        for (int s = 16; s > 0; s >>= 1) r += __shfl_down_sync(0xffffffffu, r, s);
        if (lane == 0) sm[warp][v] = r;
        float r2 = accd[v];
        for (int s = 16; s > 0; s >>= 1) r2 += __shfl_down_sync(0xffffffffu, r2, s);
        if (lane == 0) sm[warp][80+v] = r2;
    }
    #pragma unroll
    for (int v = 0; v < 8; v++) {
        float r = qn[v];
        for (int s = 16; s > 0; s >>= 1) r += __shfl_down_sync(0xffffffffu, r, s);
        if (lane == 0) sm[warp][64+v] = r;
        float r2 = knr[v];
        for (int s = 16; s > 0; s >>= 1) r2 += __shfl_down_sync(0xffffffffu, r2, s);
        if (lane == 0) sm[warp][72+v] = r2;
        float r3 = knd[v];
        for (int s = 16; s > 0; s >>= 1) r3 += __shfl_down_sync(0xffffffffu, r3, s);
        if (lane == 0) sm[warp][144+v] = r3;
    }
    __syncthreads();
    if (threadIdx.x < 160) {
        int which = threadIdx.x / 80;
        int t = threadIdx.x - which*80;
        int col;
        if (which == 0) col = t;
        else            col = (t < 64) ? 80 + t : (t < 72 ? t : 72 + t);
        float s = 0.f;
        #pragma unroll
        for (int wg = 0; wg < 8; wg++) s += sm[wg][col];
        g_part[which][bh][chunk][t] = s;
    }
}

// ---------------- finish reduction + softmax ----------------
__global__ void attn_k(const float* __restrict__ temp) {
    int which = blockIdx.x >> 5;
    int bh    = blockIdx.x & 31;
    int h     = bh & 7;
    __shared__ float sm[80];
    if (threadIdx.x < 80) {
        float s = 0.f;
        #pragma unroll
        for (int ch = 0; ch < NCHUNK; ch++) s += g_part[which][bh][ch][threadIdx.x];
        sm[threadIdx.x] = s;
    }
    __syncthreads();
    if (threadIdx.x < 8) {
        int c = threadIdx.x;
        float t  = temp[h];
        float nq = fmaxf(sqrtf(sm[64+c]), 1e-12f);
        float srow[8];
        #pragma unroll
        for (int d = 0; d < 8; d++) {
            float nk = fmaxf(sqrtf(sm[72+d]), 1e-12f);
            float s = sm[d*8+c] / nk;
            if (which == 0) s /= nq;
            srow[d] = s * t;
        }
        float mx = srow[0];
        #pragma unroll
        for (int d = 1; d < 8; d++) mx = fmaxf(mx, srow[d]);
        float sum = 0.f;
        #pragma unroll
        for (int d = 0; d < 8; d++) { srow[d] = __expf(srow[d]-mx); sum += srow[d]; }
        float inv = 1.f / sum;
        #pragma unroll
        for (int d = 0; d < 8; d++) g_attn[which][bh][c*8+d] = srow[d]*inv;
    }
}

// ---------------- fused epilogue (R7 version, f32x2, 2 px/thread) ----------------
__global__ __launch_bounds__(256) void final_k(const float* __restrict__ wproj,
                                               float* __restrict__ out) {
    __shared__ ull sA1[512], sA2[512];
    __shared__ ull sW[4096];
    int b = blockIdx.y;
    for (int i = threadIdx.x; i < 512; i += 256) {
        float a1 = g_attn[0][b*8 + (i>>6)][i & 63];
        float a2 = g_attn[1][b*8 + (i>>6)][i & 63];
        sA1[i] = pk(a1, a1);
        sA2[i] = pk(a2, a2);
    }
    for (int i = threadIdx.x; i < 4096; i += 256) {
        float wv = wproj[i];
        sW[i] = pk(wv, wv);
    }
    __syncthreads();

    int n = (blockIdx.x*256 + threadIdx.x)*2;
    const float* vr = g_kvr + ((size_t)b*128 + 64)*HWN + n;
    const float* vd = g_kvd + ((size_t)b*128 + 64)*HWN + n;

    ull p[64];
    #pragma unroll 1
    for (int h = 0; h < 8; h++) {
        ull os[8], oc[8];
        #pragma unroll
        for (int c = 0; c < 8; c++) { os[c] = 0ULL; oc[c] = 0ULL; }
        #pragma unroll
        for (int d = 0; d < 8; d++) {
            float2 r2 = *(const float2*)(vr + (size_t)(h*8+d)*HWN);
            float2 d2 = *(const float2*)(vd + (size_t)(h*8+d)*HWN);
            ull rr = pk(r2.x, r2.y);
            ull dd = pk(d2.x, d2.y);
            #pragma unroll
            for (int c = 0; c < 8; c++) {
                ffma2(os[c], sA1[h*64 + c*8 + d], rr);
                ffma2(oc[c], sA2[h*64 + c*8 + d], dd);
            }
        }
        #pragma unroll
        for (int c = 0; c < 8; c++) p[h*8+c] = fmul2(os[c], oc[c]);
    }

    float* ob = out + (size_t)b*64*HWN + n;
    #pragma unroll 4
    for (int o = 0; o < 64; o++) {
        ull acc = 0ULL;
        const ull* wr = sW + o*64;
        #pragma unroll
        for (int c = 0; c < 64; c++) ffma2(acc, wr[c], p[c]);
        float2 r; upk(r.x, r.y, acc);
        *(float2*)(ob + (size_t)o*HWN) = r;
    }
}

// ---------------- host launch ----------------
extern "C" void kernel_launch(void* const* d_in, const int* in_sizes, int n_in,
                              void* d_out, int out_size) {
    const float* rgb   = (const float*)d_in[0];
    const float* depth = (const float*)d_in[1];
    const float* temp  = (const float*)d_in[2];
    const float* wqr   = (const float*)d_in[3];
    const float* wqd   = (const float*)d_in[4];
    const float* wqc   = (const float*)d_in[5];
    const float* w1    = (const float*)d_in[6];
    const float* w5    = (const float*)d_in[7];
    const float* w7    = (const float*)d_in[8];
    const float* w9    = (const float*)d_in[9];
    const float* wproj = (const float*)d_in[10];
    float* out = (float*)d_out;

    void* p;
    cudaGetSymbolAddress(&p, g_qrgb); float* qrg = (float*)p;
    cudaGetSymbolAddress(&p, g_kvr);  float* kvr = (float*)p;
    cudaGetSymbolAddress(&p, g_kvd);  float* kvd = (float*)p;

    const int T = 256;
    const int MFE_BACK_SMEM = (10400 + 9360) * 4;   // 79040 B
    cudaFuncSetAttribute(mfe_back_k, cudaFuncAttributeMaxDynamicSharedMemorySize, MFE_BACK_SMEM);

    // ---- MFE (2 fused kernels) ----
    dim3 fgk(9, BB*CC);
    mfe_front_k<<<fgk, T>>>(rgb);
    dim3 bgk(8, BB*CC);
    mfe_back_k<<<bgk, T, MFE_BACK_SMEM>>>(w1, w5, w7, w9);

    // ---- kv paths: both modalities in one launch each ----
    dim3 cg(HWN/(T*4), BB, 2);
    conv1x1_duo_k<<<cg, T>>>(rgb, depth, wqr, wqd);
    dim3 dg(4, BB*128, 2);               // 4 strips of 64 rows, 512 planes, 2 modalities
    dw3_duo_k<<<dg, T>>>(wqc);

    // ---- attention statistics ----
    dim3 rg(NCHUNK, 32);
    reduce_qk2_k<<<rg, T>>>(qrg, kvr, kvd);
    attn_k<<<64, 128>>>(temp);

    // ---- fused epilogue ----
    dim3 fg(HWN/(T*2), BB);
    final_k<<<fg, T>>>(wproj, out);
}

// round 10
// speedup vs baseline: 1.3743x; 1.0715x over previous
#include <cuda_runtime.h>

#define BB 4
#define CC 64
#define HH 256
#define WW 256
#define HWN 65536
#define HO 130
#define NCHUNK 32

typedef unsigned long long ull;

// ---------------- scratch (device globals; no allocations) ----------------
__device__ float g_qrgb[BB*CC*HWN];
__device__ float g_s  [4][BB*CC*HO*HO];
__device__ float g_cvt0[BB*2*CC*HWN];
__device__ float g_cvt1[BB*2*CC*HWN];
__device__ float g_kvr[BB*2*CC*HWN];
__device__ float g_kvd[BB*2*CC*HWN];
__device__ float g_part[2][32][NCHUNK][80];
__device__ float g_attn[2][32][64];

// db3 filters
__constant__ float c_DEC_LO[6] = { 0.035226291882100656f, -0.08544127388224149f, -0.13501102001039084f,
                                   0.4598775021193313f,    0.8068915093133388f,   0.3326705529509569f };
__constant__ float c_DEC_HI[6] = {-0.3326705529509569f,    0.8068915093133388f,  -0.4598775021193313f,
                                  -0.13501102001039084f,   0.08544127388224149f,  0.035226291882100656f };
__constant__ float c_REC_LO[6] = { 0.3326705529509569f,    0.8068915093133388f,   0.4598775021193313f,
                                  -0.13501102001039084f,  -0.08544127388224149f,  0.035226291882100656f };
__constant__ float c_REC_HI[6] = { 0.035226291882100656f,  0.08544127388224149f, -0.13501102001039084f,
                                  -0.4598775021193313f,    0.8068915093133388f,  -0.3326705529509569f };

// ---------------- packed f32x2 helpers ----------------
__device__ __forceinline__ ull pk(float lo, float hi) {
    ull r;
    asm("mov.b64 %0, {%1, %2};" : "=l"(r) : "r"(__float_as_uint(lo)), "r"(__float_as_uint(hi)));
    return r;
}
__device__ __forceinline__ void upk(float& lo, float& hi, ull v) {
    unsigned a, b;
    asm("mov.b64 {%0, %1}, %2;" : "=r"(a), "=r"(b) : "l"(v));
    lo = __uint_as_float(a); hi = __uint_as_float(b);
}
__device__ __forceinline__ void ffma2(ull& d, ull a, ull b) {
    asm("fma.rn.f32x2 %0, %1, %2, %0;" : "+l"(d) : "l"(a), "l"(b));
}
__device__ __forceinline__ ull fmul2(ull a, ull b) {
    ull r; asm("mul.rn.f32x2 %0, %1, %2;" : "=l"(r) : "l"(a), "l"(b)); return r;
}

// ================= fused DWT (rows+cols): rgb -> 4 subbands =================
__global__ __launch_bounds__(256) void mfe_front_k(const float* __restrict__ x) {
    __shared__ float sLo[36*130], sHi[36*130];
    int bc = blockIdx.y;
    int i0 = blockIdx.x * 16;
    int iCnt = min(16, HO - i0);
    int rbase = max(0, 2*i0 - 4);
    int rend  = min(HH-1, 2*(i0 + iCnt - 1) + 1);
    int nR = rend - rbase + 1;
    const float* plane = x + ((size_t)bc << 16);

    for (int idx = threadIdx.x; idx < nR*130; idx += 256) {
        int rl = idx / 130, j = idx - rl*130;
        const float* row = plane + ((rbase + rl) << 8);
        float lo = 0.f, hi = 0.f;
        int base = 2*j - 4;
        #pragma unroll
        for (int s = 0; s < 6; s++) {
            int col = base + s;
            if (col >= 0 && col < WW) {
                float v = row[col];
                lo += v * c_REC_LO[s];
                hi += v * c_REC_HI[s];
            }
        }
        sLo[idx] = lo; sHi[idx] = hi;
    }
    __syncthreads();

    size_t obase = (size_t)bc * (HO*HO);
    for (int idx = threadIdx.x; idx < iCnt*130; idx += 256) {
        int il = idx / 130, xc = idx - il*130;
        int i = i0 + il;
        float ll=0.f, lh=0.f, hl=0.f, hh=0.f;
        int rb = 2*i - 4;
        #pragma unroll
        for (int t = 0; t < 6; t++) {
            int r = rb + t;
            if (r >= 0 && r < HH) {
                int rl = r - rbase;
                float vl = sLo[rl*130 + xc], vh = sHi[rl*130 + xc];
                ll += vl*c_REC_LO[t]; lh += vl*c_REC_HI[t];
                hl += vh*c_REC_LO[t]; hh += vh*c_REC_HI[t];
            }
        }
        size_t o = obase + (size_t)i*HO + xc;
        g_s[0][o]=ll; g_s[1][o]=lh; g_s[2][o]=hl; g_s[3][o]=hh;
    }
}

// ======= fused dw3(subbands) + IDWT(cols+rows): 4 subbands -> qrgb =======
__global__ __launch_bounds__(256) void mfe_back_k(const float* __restrict__ w1, const float* __restrict__ w5,
                                                  const float* __restrict__ w7, const float* __restrict__ w9) {
    extern __shared__ float sdyn[];
    float* sRaw  = sdyn;
    float* sPost = sdyn + 10400;
    __shared__ float sW[36];

    int bc = blockIdx.y;
    int c  = bc & 63;
    int m0 = blockIdx.x * 32;
    int jp0 = m0 >> 1;
    int jr0 = max(0, jp0 - 1);
    int jr1 = min(HO-1, jp0 + 18);
    int nJr = jr1 - jr0 + 1;

    if (threadIdx.x < 36) {
        int s = threadIdx.x / 9, k = threadIdx.x - s*9;
        const float* wp = (s==0) ? w1 : (s==1) ? w5 : (s==2) ? w7 : w9;
        sW[threadIdx.x] = wp[c*9 + k];
    }

    size_t sbase = (size_t)bc * (HO*HO);
    int nElems = 4*nJr*130;
    for (int idx = threadIdx.x; idx < nElems; idx += 256) {
        int s = idx / (nJr*130);
        int rem = idx - s*nJr*130;
        int rl = rem / 130, xc = rem - rl*130;
        sRaw[s*(20*130) + rl*130 + xc] = g_s[s][sbase + (size_t)(jr0+rl)*HO + xc];
    }
    __syncthreads();

    for (int idx = threadIdx.x; idx < 4*18*130; idx += 256) {
        int s = idx / (18*130);
        int rem = idx - s*(18*130);
        int pl = rem / 130, xc = rem - pl*130;
        int jglob = jp0 + pl;
        const float* wr = sW + s*9;
        const float* rb = sRaw + s*(20*130);
        float acc = 0.f;
        #pragma unroll
        for (int dy = -1; dy <= 1; dy++) {
            int jn = jglob + dy;
            if (jn < 0 || jn >= HO) continue;
            int rl = jn - jr0;
            #pragma unroll
            for (int dx = -1; dx <= 1; dx++) {
                int xn = xc + dx;
                if (xn < 0 || xn >= HO) continue;
                acc += rb[rl*130 + xn] * wr[(dy+1)*3 + (dx+1)];
            }
        }
        sPost[idx] = acc;
    }
    __syncthreads();

    float* sL2 = sRaw;
    float* sH2 = sRaw + 4160;
    for (int idx = threadIdx.x; idx < 32*130; idx += 256) {
        int ml = idx / 130, xc = idx - ml*130;
        int m = m0 + ml;
        int i0f = (m & 1) ? 0 : 1;
        int jl = (m >> 1) - jp0;
        float lo = 0.f, hi = 0.f;
        #pragma unroll
        for (int t = 0; t < 3; t++) {
            int fi = i0f + 2*t;
            int pr = jl + t;
            float a0 = sPost[0*(18*130) + pr*130 + xc];
            float a1 = sPost[1*(18*130) + pr*130 + xc];
            float a2 = sPost[2*(18*130) + pr*130 + xc];
            float a3 = sPost[3*(18*130) + pr*130 + xc];
            lo += a0*c_DEC_LO[fi] + a1*c_DEC_HI[fi];
            hi += a2*c_DEC_LO[fi] + a3*c_DEC_HI[fi];
        }
        sL2[idx] = lo; sH2[idx] = hi;
    }
    __syncthreads();

    float* oplane = g_qrgb + ((size_t)bc << 16);
    for (int idx = threadIdx.x; idx < 32*256; idx += 256) {
        int ml = idx >> 8, w = idx & 255;
        int i0f = (w & 1) ? 0 : 1;
        int j0w = w >> 1;
        const float* lrow = sL2 + ml*130;
        const float* hrow = sH2 + ml*130;
        float acc = 0.f;
        #pragma unroll
        for (int t = 0; t < 3; t++) {
            int fi = i0f + 2*t;
            acc += lrow[j0w+t]*c_DEC_LO[fi] + hrow[j0w+t]*c_DEC_HI[fi];
        }
        oplane[((m0 + ml) << 8) + w] = acc;
    }
}

// ======== 1x1 conv 64->128 (single modality; dup weights, broadcast LDS) ========
__global__ __launch_bounds__(256) void conv1x1_k(const float* __restrict__ in,
                                                 const float* __restrict__ w,
                                                 float* __restrict__ out) {
    __shared__ ull sw2[64*64];
    int b = blockIdx.y;
    int pb = (blockIdx.x*256 + threadIdx.x)*4;
    const float* ib = in  + (size_t)b*CC*HWN + pb;
    float*       ob = out + (size_t)b*(2*CC)*HWN + pb;

    for (int half = 0; half < 2; half++) {
        for (int i = threadIdx.x; i < 4096; i += 256) {
            float wv = w[half*4096 + i];
            sw2[i] = pk(wv, wv);
        }
        __syncthreads();
        #pragma unroll 1
        for (int ot = 0; ot < 4; ot++) {
            ull a0[16], a1[16];
            #pragma unroll
            for (int o = 0; o < 16; o++) { a0[o] = 0ULL; a1[o] = 0ULL; }
            #pragma unroll 4
            for (int c = 0; c < 64; c++) {
                float4 x = *(const float4*)(ib + (size_t)c*HWN);
                ull x01 = pk(x.x, x.y), x23 = pk(x.z, x.w);
                const ull* wr = sw2 + (ot*16)*64 + c;
                #pragma unroll
                for (int o = 0; o < 16; o++) {
                    ull wv = wr[o*64];
                    ffma2(a0[o], wv, x01);
                    ffma2(a1[o], wv, x23);
                }
            }
            #pragma unroll
            for (int o = 0; o < 16; o++) {
                float4 r;
                upk(r.x, r.y, a0[o]);
                upk(r.z, r.w, a1[o]);
                *(float4*)(ob + (size_t)(half*64 + ot*16 + o)*HWN) = r;
            }
        }
        __syncthreads();
    }
}

// ======== depthwise 3x3, shuffle edges, 8 px/thread, rolling rows ========
struct Row8 {
    float4 A, B;
    float pw, nx;
};
__device__ __forceinline__ Row8 load_row8(const float* plane, int y, int lane) {
    Row8 r;
    if (y < 0 || y >= HH) {
        r.A = make_float4(0.f,0.f,0.f,0.f);
        r.B = r.A; r.pw = 0.f; r.nx = 0.f;
        float pw = __shfl_up_sync(0xffffffffu, 0.f, 1);
        float nx = __shfl_down_sync(0xffffffffu, 0.f, 1);
        (void)pw; (void)nx;
        return r;
    }
    const float* p = plane + (y << 8) + (lane << 3);
    r.A = *(const float4*)p;
    r.B = *(const float4*)(p + 4);
    float pw = __shfl_up_sync(0xffffffffu, r.B.w, 1);
    float nx = __shfl_down_sync(0xffffffffu, r.A.x, 1);
    r.pw = (lane == 0)  ? 0.f : pw;
    r.nx = (lane == 31) ? 0.f : nx;
    return r;
}
__device__ __forceinline__ void acc_row8(float* acc, const Row8& r, float wa, float wb, float wc) {
    acc[0] += wa*r.pw  + wb*r.A.x + wc*r.A.y;
    acc[1] += wa*r.A.x + wb*r.A.y + wc*r.A.z;
    acc[2] += wa*r.A.y + wb*r.A.z + wc*r.A.w;
    acc[3] += wa*r.A.z + wb*r.A.w + wc*r.B.x;
    acc[4] += wa*r.A.w + wb*r.B.x + wc*r.B.y;
    acc[5] += wa*r.B.x + wb*r.B.y + wc*r.B.z;
    acc[6] += wa*r.B.y + wb*r.B.z + wc*r.B.w;
    acc[7] += wa*r.B.z + wb*r.B.w + wc*r.nx;
}

// grid: (4 strips of 64 rows, 512 planes). warp handles 8 rows.
__global__ __launch_bounds__(256) void dw3_k(const float* __restrict__ in,
                                             const float* __restrict__ wt,
                                             float* __restrict__ out) {
    int bc = blockIdx.y;
    int c  = bc & 127;
    int warp = threadIdx.x >> 5, lane = threadIdx.x & 31;
    int yb = blockIdx.x*64 + warp*8;

    float w[9];
    #pragma unroll
    for (int k = 0; k < 9; k++) w[k] = wt[c*9 + k];

    const float* plane = in  + ((size_t)bc << 16);
    float*      oplane = out + ((size_t)bc << 16);

    Row8 rp = load_row8(plane, yb - 1, lane);
    Row8 rc = load_row8(plane, yb,     lane);
    #pragma unroll
    for (int i = 0; i < 8; i++) {
        Row8 rn = load_row8(plane, yb + i + 1, lane);
        float acc[8];
        #pragma unroll
        for (int k = 0; k < 8; k++) acc[k] = 0.f;
        acc_row8(acc, rp, w[0], w[1], w[2]);
        acc_row8(acc, rc, w[3], w[4], w[5]);
        acc_row8(acc, rn, w[6], w[7], w[8]);
        float* op = oplane + ((yb + i) << 8) + (lane << 3);
        *(float4*)op       = make_float4(acc[0], acc[1], acc[2], acc[3]);
        *(float4*)(op + 4) = make_float4(acc[4], acc[5], acc[6], acc[7]);
        rp = rc; rc = rn;
    }
}

// ---------- fused Gram reduction: q read once, both modalities ----------
__global__ __launch_bounds__(256, 1) void reduce_qk2_k(const float* __restrict__ q,
                                                       const float* __restrict__ kvr,
                                                       const float* __restrict__ kvd) {
    int chunk = blockIdx.x;
    int bh    = blockIdx.y;
    int b = bh >> 3, h = bh & 7;
    size_t qoff = ((size_t)b*64  + h*8)*HWN;
    size_t koff = ((size_t)b*128 + h*8)*HWN;

    float accr[64], accd[64], qn[8], knr[8], knd[8];
    #pragma unroll
    for (int i = 0; i < 64; i++) { accr[i] = 0.f; accd[i] = 0.f; }
    #pragma unroll
    for (int i = 0; i < 8; i++) { qn[i] = 0.f; knr[i] = 0.f; knd[i] = 0.f; }

    const int CS4 = HWN / NCHUNK / 4;
    int start = chunk * CS4;
    for (int it = threadIdx.x; it < CS4; it += blockDim.x) {
        int idx = start + it;
        float4 qv[8];
        #pragma unroll
        for (int c = 0; c < 8; c++) {
            qv[c] = ((const float4*)(q + qoff + (size_t)c*HWN))[idx];
            qn[c] += qv[c].x*qv[c].x + qv[c].y*qv[c].y + qv[c].z*qv[c].z + qv[c].w*qv[c].w;
        }
        #pragma unroll
        for (int d = 0; d < 8; d++) {
            float4 k4 = ((const float4*)(kvr + koff + (size_t)d*HWN))[idx];
            knr[d] += k4.x*k4.x + k4.y*k4.y + k4.z*k4.z + k4.w*k4.w;
            #pragma unroll
            for (int c = 0; c < 8; c++)
                accr[d*8+c] += qv[c].x*k4.x + qv[c].y*k4.y + qv[c].z*k4.z + qv[c].w*k4.w;
        }
        #pragma unroll
        for (int d = 0; d < 8; d++) {
            float4 k4 = ((const float4*)(kvd + koff + (size_t)d*HWN))[idx];
            knd[d] += k4.x*k4.x + k4.y*k4.y + k4.z*k4.z + k4.w*k4.w;
            #pragma unroll
            for (int c = 0; c < 8; c++)
                accd[d*8+c] += qv[c].x*k4.x + qv[c].y*k4.y + qv[c].z*k4.z + qv[c].w*k4.w;
        }
    }

    __shared__ float sm[8][152];
    int lane = threadIdx.x & 31, warp = threadIdx.x >> 5;
    #pragma unroll
    for (int v = 0; v < 64; v++) {
        float r = accr[v];
        for (int s = 16; s > 0; s >>= 1) r += __shfl_down_sync(0xffffffffu, r, s);
        if (lane == 0) sm[warp][v] = r;
        float r2 = accd[v];
        for (int s = 16; s > 0; s >>= 1) r2 += __shfl_down_sync(0xffffffffu, r2, s);
        if (lane == 0) sm[warp][80+v] = r2;
    }
    #pragma unroll
    for (int v = 0; v < 8; v++) {
        float r = qn[v];
        for (int s = 16; s > 0; s >>= 1) r += __shfl_down_sync(0xffffffffu, r, s);
        if (lane == 0) sm[warp][64+v] = r;
        float r2 = knr[v];
        for (int s = 16; s > 0; s >>= 1) r2 += __shfl_down_sync(0xffffffffu, r2, s);
        if (lane == 0) sm[warp][72+v] = r2;
        float r3 = knd[v];
        for (int s = 16; s > 0; s >>= 1) r3 += __shfl_down_sync(0xffffffffu, r3, s);
        if (lane == 0) sm[warp][144+v] = r3;
    }
    __syncthreads();
    if (threadIdx.x < 160) {
        int which = threadIdx.x / 80;
        int t = threadIdx.x - which*80;
        int col;
        if (which == 0) col = t;
        else            col = (t < 64) ? 80 + t : (t < 72 ? t : 72 + t);
        float s = 0.f;
        #pragma unroll
        for (int wg = 0; wg < 8; wg++) s += sm[wg][col];
        g_part[which][bh][chunk][t] = s;
    }
}

// ---------------- finish reduction + softmax ----------------
__global__ void attn_k(const float* __restrict__ temp) {
    int which = blockIdx.x >> 5;
    int bh    = blockIdx.x & 31;
    int h     = bh & 7;
    __shared__ float sm[80];
    if (threadIdx.x < 80) {
        float s = 0.f;
        #pragma unroll
        for (int ch = 0; ch < NCHUNK; ch++) s += g_part[which][bh][ch][threadIdx.x];
        sm[threadIdx.x] = s;
    }
    __syncthreads();
    if (threadIdx.x < 8) {
        int c = threadIdx.x;
        float t  = temp[h];
        float nq = fmaxf(sqrtf(sm[64+c]), 1e-12f);
        float srow[8];
        #pragma unroll
        for (int d = 0; d < 8; d++) {
            float nk = fmaxf(sqrtf(sm[72+d]), 1e-12f);
            float s = sm[d*8+c] / nk;
            if (which == 0) s /= nq;
            srow[d] = s * t;
        }
        float mx = srow[0];
        #pragma unroll
        for (int d = 1; d < 8; d++) mx = fmaxf(mx, srow[d]);
        float sum = 0.f;
        #pragma unroll
        for (int d = 0; d < 8; d++) { srow[d] = __expf(srow[d]-mx); sum += srow[d]; }
        float inv = 1.f / sum;
        #pragma unroll
        for (int d = 0; d < 8; d++) g_attn[which][bh][c*8+d] = srow[d]*inv;
    }
}

// ---------------- fused epilogue (f32x2, 2 px/thread) ----------------
__global__ __launch_bounds__(256) void final_k(const float* __restrict__ wproj,
                                               float* __restrict__ out) {
    __shared__ ull sA1[512], sA2[512];
    __shared__ ull sW[4096];
    int b = blockIdx.y;
    for (int i = threadIdx.x; i < 512; i += 256) {
        float a1 = g_attn[0][b*8 + (i>>6)][i & 63];
        float a2 = g_attn[1][b*8 + (i>>6)][i & 63];
        sA1[i] = pk(a1, a1);
        sA2[i] = pk(a2, a2);
    }
    for (int i = threadIdx.x; i < 4096; i += 256) {
        float wv = wproj[i];
        sW[i] = pk(wv, wv);
    }
    __syncthreads();

    int n = (blockIdx.x*256 + threadIdx.x)*2;
    const float* vr = g_kvr + ((size_t)b*128 + 64)*HWN + n;
    const float* vd = g_kvd + ((size_t)b*128 + 64)*HWN + n;

    ull p[64];
    #pragma unroll 1
    for (int h = 0; h < 8; h++) {
        ull os[8], oc[8];
        #pragma unroll
        for (int c = 0; c < 8; c++) { os[c] = 0ULL; oc[c] = 0ULL; }
        #pragma unroll
        for (int d = 0; d < 8; d++) {
            float2 r2 = *(const float2*)(vr + (size_t)(h*8+d)*HWN);
            float2 d2 = *(const float2*)(vd + (size_t)(h*8+d)*HWN);
            ull rr = pk(r2.x, r2.y);
            ull dd = pk(d2.x, d2.y);
            #pragma unroll
            for (int c = 0; c < 8; c++) {
                ffma2(os[c], sA1[h*64 + c*8 + d], rr);
                ffma2(oc[c], sA2[h*64 + c*8 + d], dd);
            }
        }
        #pragma unroll
        for (int c = 0; c < 8; c++) p[h*8+c] = fmul2(os[c], oc[c]);
    }

    float* ob = out + (size_t)b*64*HWN + n;
    #pragma unroll 4
    for (int o = 0; o < 64; o++) {
        ull acc = 0ULL;
        const ull* wr = sW + o*64;
        #pragma unroll
        for (int c = 0; c < 64; c++) ffma2(acc, wr[c], p[c]);
        float2 r; upk(r.x, r.y, acc);
        *(float2*)(ob + (size_t)o*HWN) = r;
    }
}

// ---------------- host launch ----------------
extern "C" void kernel_launch(void* const* d_in, const int* in_sizes, int n_in,
                              void* d_out, int out_size) {
    const float* rgb   = (const float*)d_in[0];
    const float* depth = (const float*)d_in[1];
    const float* temp  = (const float*)d_in[2];
    const float* wqr   = (const float*)d_in[3];
    const float* wqd   = (const float*)d_in[4];
    const float* wqc   = (const float*)d_in[5];
    const float* w1    = (const float*)d_in[6];
    const float* w5    = (const float*)d_in[7];
    const float* w7    = (const float*)d_in[8];
    const float* w9    = (const float*)d_in[9];
    const float* wproj = (const float*)d_in[10];
    float* out = (float*)d_out;

    void* p;
    cudaGetSymbolAddress(&p, g_qrgb); float* qrg  = (float*)p;
    cudaGetSymbolAddress(&p, g_cvt0); float* cvt0 = (float*)p;
    cudaGetSymbolAddress(&p, g_cvt1); float* cvt1 = (float*)p;
    cudaGetSymbolAddress(&p, g_kvr);  float* kvr  = (float*)p;
    cudaGetSymbolAddress(&p, g_kvd);  float* kvd  = (float*)p;

    // init-once side streams + events (host objects only; no device work here)
    static cudaStream_t s1 = 0, s2 = 0;
    static cudaEvent_t evFork1 = 0, evFork2 = 0, evMfe = 0, evDep = 0;
    if (!s1) {
        cudaStreamCreateWithFlags(&s1, cudaStreamNonBlocking);
        cudaStreamCreateWithFlags(&s2, cudaStreamNonBlocking);
        cudaEventCreateWithFlags(&evFork1, cudaEventDisableTiming);
        cudaEventCreateWithFlags(&evFork2, cudaEventDisableTiming);
        cudaEventCreateWithFlags(&evMfe,  cudaEventDisableTiming);
        cudaEventCreateWithFlags(&evDep,  cudaEventDisableTiming);
    }

    const int T = 256;
    const int MFE_BACK_SMEM = (10400 + 9360) * 4;   // 79040 B
    cudaFuncSetAttribute(mfe_back_k, cudaFuncAttributeMaxDynamicSharedMemorySize, MFE_BACK_SMEM);

    // fork: main(0) -> s1 (mfe), s2 (depth chain)
    cudaEventRecord(evFork1, 0);
    cudaStreamWaitEvent(s1, evFork1, 0);
    cudaEventRecord(evFork2, 0);
    cudaStreamWaitEvent(s2, evFork2, 0);

    // ---- branch s1: MFE ----
    dim3 fgk(9, BB*CC);
    mfe_front_k<<<fgk, T, 0, s1>>>(rgb);
    dim3 bgk(8, BB*CC);
    mfe_back_k<<<bgk, T, MFE_BACK_SMEM, s1>>>(w1, w5, w7, w9);
    cudaEventRecord(evMfe, s1);

    // ---- branch s2: depth conv -> dw3 ----
    dim3 cg(HWN/(T*4), BB);
    dim3 dg(4, BB*128);
    conv1x1_k<<<cg, T, 0, s2>>>(depth, wqd, cvt1);
    dw3_k<<<dg, T, 0, s2>>>(cvt1, wqc, kvd);
    cudaEventRecord(evDep, s2);

    // ---- main stream: rgb conv -> dw3 ----
    conv1x1_k<<<cg, T>>>(rgb, wqr, cvt0);
    dw3_k<<<dg, T>>>(cvt0, wqc, kvr);

    // join both branches into main stream
    cudaStreamWaitEvent(0, evMfe, 0);
    cudaStreamWaitEvent(0, evDep, 0);

    // ---- attention statistics ----
    dim3 rg(NCHUNK, 32);
    reduce_qk2_k<<<rg, T>>>(qrg, kvr, kvd);
    attn_k<<<64, 128>>>(temp);

    // ---- fused epilogue ----
    dim3 fg(HWN/(T*2), BB);
    final_k<<<fg, T>>>(wproj, out);
}

// round 11
// speedup vs baseline: 1.4100x; 1.0260x over previous
#include <cuda_runtime.h>

#define BB 4
#define CC 64
#define HH 256
#define WW 256
#define HWN 65536
#define HO 130
#define NCHUNK 32

typedef unsigned long long ull;

// ---------------- scratch (device globals; no allocations) ----------------
__device__ float g_qrgb[BB*CC*HWN];
__device__ float g_s  [4][BB*CC*HO*HO];
__device__ float g_cvt0[BB*2*CC*HWN];
__device__ float g_cvt1[BB*2*CC*HWN];
__device__ float g_kvr[BB*2*CC*HWN];
__device__ float g_kvd[BB*2*CC*HWN];
__device__ float g_part[2][32][NCHUNK][80];
__device__ float g_attn[2][32][64];

// db3 filters
__constant__ float c_DEC_LO[6] = { 0.035226291882100656f, -0.08544127388224149f, -0.13501102001039084f,
                                   0.4598775021193313f,    0.8068915093133388f,   0.3326705529509569f };
__constant__ float c_DEC_HI[6] = {-0.3326705529509569f,    0.8068915093133388f,  -0.4598775021193313f,
                                  -0.13501102001039084f,   0.08544127388224149f,  0.035226291882100656f };
__constant__ float c_REC_LO[6] = { 0.3326705529509569f,    0.8068915093133388f,   0.4598775021193313f,
                                  -0.13501102001039084f,  -0.08544127388224149f,  0.035226291882100656f };
__constant__ float c_REC_HI[6] = { 0.035226291882100656f,  0.08544127388224149f, -0.13501102001039084f,
                                  -0.4598775021193313f,    0.8068915093133388f,  -0.3326705529509569f };

// ---------------- packed f32x2 helpers ----------------
__device__ __forceinline__ ull pk(float lo, float hi) {
    ull r;
    asm("mov.b64 %0, {%1, %2};" : "=l"(r) : "r"(__float_as_uint(lo)), "r"(__float_as_uint(hi)));
    return r;
}
__device__ __forceinline__ void upk(float& lo, float& hi, ull v) {
    unsigned a, b;
    asm("mov.b64 {%0, %1}, %2;" : "=r"(a), "=r"(b) : "l"(v));
    lo = __uint_as_float(a); hi = __uint_as_float(b);
}
__device__ __forceinline__ void ffma2(ull& d, ull a, ull b) {
    asm("fma.rn.f32x2 %0, %1, %2, %0;" : "+l"(d) : "l"(a), "l"(b));
}
__device__ __forceinline__ ull fmul2(ull a, ull b) {
    ull r; asm("mul.rn.f32x2 %0, %1, %2;" : "=l"(r) : "l"(a), "l"(b)); return r;
}

// ================= fused DWT (rows+cols): rgb -> 4 subbands =================
__global__ __launch_bounds__(256) void mfe_front_k(const float* __restrict__ x) {
    __shared__ float sLo[36*130], sHi[36*130];
    int bc = blockIdx.y;
    int i0 = blockIdx.x * 16;
    int iCnt = min(16, HO - i0);
    int rbase = max(0, 2*i0 - 4);
    int rend  = min(HH-1, 2*(i0 + iCnt - 1) + 1);
    int nR = rend - rbase + 1;
    const float* plane = x + ((size_t)bc << 16);

    for (int idx = threadIdx.x; idx < nR*130; idx += 256) {
        int rl = idx / 130, j = idx - rl*130;
        const float* row = plane + ((rbase + rl) << 8);
        float lo = 0.f, hi = 0.f;
        int base = 2*j - 4;
        #pragma unroll
        for (int s = 0; s < 6; s++) {
            int col = base + s;
            if (col >= 0 && col < WW) {
                float v = row[col];
                lo += v * c_REC_LO[s];
                hi += v * c_REC_HI[s];
            }
        }
        sLo[idx] = lo; sHi[idx] = hi;
    }
    __syncthreads();

    size_t obase = (size_t)bc * (HO*HO);
    for (int idx = threadIdx.x; idx < iCnt*130; idx += 256) {
        int il = idx / 130, xc = idx - il*130;
        int i = i0 + il;
        float ll=0.f, lh=0.f, hl=0.f, hh=0.f;
        int rb = 2*i - 4;
        #pragma unroll
        for (int t = 0; t < 6; t++) {
            int r = rb + t;
            if (r >= 0 && r < HH) {
                int rl = r - rbase;
                float vl = sLo[rl*130 + xc], vh = sHi[rl*130 + xc];
                ll += vl*c_REC_LO[t]; lh += vl*c_REC_HI[t];
                hl += vh*c_REC_LO[t]; hh += vh*c_REC_HI[t];
            }
        }
        size_t o = obase + (size_t)i*HO + xc;
        g_s[0][o]=ll; g_s[1][o]=lh; g_s[2][o]=hl; g_s[3][o]=hh;
    }
}

// ======= fused dw3(subbands) + IDWT(cols+rows): 4 subbands -> qrgb =======
__global__ __launch_bounds__(256) void mfe_back_k(const float* __restrict__ w1, const float* __restrict__ w5,
                                                  const float* __restrict__ w7, const float* __restrict__ w9) {
    extern __shared__ float sdyn[];
    float* sRaw  = sdyn;
    float* sPost = sdyn + 10400;
    __shared__ float sW[36];

    int bc = blockIdx.y;
    int c  = bc & 63;
    int m0 = blockIdx.x * 32;
    int jp0 = m0 >> 1;
    int jr0 = max(0, jp0 - 1);
    int jr1 = min(HO-1, jp0 + 18);
    int nJr = jr1 - jr0 + 1;

    if (threadIdx.x < 36) {
        int s = threadIdx.x / 9, k = threadIdx.x - s*9;
        const float* wp = (s==0) ? w1 : (s==1) ? w5 : (s==2) ? w7 : w9;
        sW[threadIdx.x] = wp[c*9 + k];
    }

    size_t sbase = (size_t)bc * (HO*HO);
    int nElems = 4*nJr*130;
    for (int idx = threadIdx.x; idx < nElems; idx += 256) {
        int s = idx / (nJr*130);
        int rem = idx - s*nJr*130;
        int rl = rem / 130, xc = rem - rl*130;
        sRaw[s*(20*130) + rl*130 + xc] = g_s[s][sbase + (size_t)(jr0+rl)*HO + xc];
    }
    __syncthreads();

    for (int idx = threadIdx.x; idx < 4*18*130; idx += 256) {
        int s = idx / (18*130);
        int rem = idx - s*(18*130);
        int pl = rem / 130, xc = rem - pl*130;
        int jglob = jp0 + pl;
        const float* wr = sW + s*9;
        const float* rb = sRaw + s*(20*130);
        float acc = 0.f;
        #pragma unroll
        for (int dy = -1; dy <= 1; dy++) {
            int jn = jglob + dy;
            if (jn < 0 || jn >= HO) continue;
            int rl = jn - jr0;
            #pragma unroll
            for (int dx = -1; dx <= 1; dx++) {
                int xn = xc + dx;
                if (xn < 0 || xn >= HO) continue;
                acc += rb[rl*130 + xn] * wr[(dy+1)*3 + (dx+1)];
            }
        }
        sPost[idx] = acc;
    }
    __syncthreads();

    float* sL2 = sRaw;
    float* sH2 = sRaw + 4160;
    for (int idx = threadIdx.x; idx < 32*130; idx += 256) {
        int ml = idx / 130, xc = idx - ml*130;
        int m = m0 + ml;
        int i0f = (m & 1) ? 0 : 1;
        int jl = (m >> 1) - jp0;
        float lo = 0.f, hi = 0.f;
        #pragma unroll
        for (int t = 0; t < 3; t++) {
            int fi = i0f + 2*t;
            int pr = jl + t;
            float a0 = sPost[0*(18*130) + pr*130 + xc];
            float a1 = sPost[1*(18*130) + pr*130 + xc];
            float a2 = sPost[2*(18*130) + pr*130 + xc];
            float a3 = sPost[3*(18*130) + pr*130 + xc];
            lo += a0*c_DEC_LO[fi] + a1*c_DEC_HI[fi];
            hi += a2*c_DEC_LO[fi] + a3*c_DEC_HI[fi];
        }
        sL2[idx] = lo; sH2[idx] = hi;
    }
    __syncthreads();

    float* oplane = g_qrgb + ((size_t)bc << 16);
    for (int idx = threadIdx.x; idx < 32*256; idx += 256) {
        int ml = idx >> 8, w = idx & 255;
        int i0f = (w & 1) ? 0 : 1;
        int j0w = w >> 1;
        const float* lrow = sL2 + ml*130;
        const float* hrow = sH2 + ml*130;
        float acc = 0.f;
        #pragma unroll
        for (int t = 0; t < 3; t++) {
            int fi = i0f + 2*t;
            acc += lrow[j0w+t]*c_DEC_LO[fi] + hrow[j0w+t]*c_DEC_HI[fi];
        }
        oplane[((m0 + ml) << 8) + w] = acc;
    }
}

// ======== 1x1 conv 64->128: transposed packed weights, LDS.128 broadcasts ========
__global__ __launch_bounds__(256) void conv1x1_k(const float* __restrict__ in,
                                                 const float* __restrict__ w,
                                                 float* __restrict__ out) {
    __shared__ ull swT[64*64];   // [c][o_local] packed; one 64-output half at a time
    int b = blockIdx.y;
    int pb = (blockIdx.x*256 + threadIdx.x)*4;
    const float* ib = in  + (size_t)b*CC*HWN + pb;
    float*       ob = out + (size_t)b*(2*CC)*HWN + pb;

    for (int half = 0; half < 2; half++) {
        for (int i = threadIdx.x; i < 4096; i += 256) {
            int c = i >> 6, o = i & 63;                 // swT[c*64 + o]
            float wv = w[half*4096 + o*64 + c];
            swT[i] = pk(wv, wv);
        }
        __syncthreads();
        #pragma unroll 1
        for (int ot = 0; ot < 4; ot++) {
            ull a0[16], a1[16];
            #pragma unroll
            for (int o = 0; o < 16; o++) { a0[o] = 0ULL; a1[o] = 0ULL; }
            #pragma unroll 4
            for (int c = 0; c < 64; c++) {
                float4 x = *(const float4*)(ib + (size_t)c*HWN);
                ull x01 = pk(x.x, x.y), x23 = pk(x.z, x.w);
                const ulonglong2* wr = (const ulonglong2*)(swT + (c << 6) + (ot << 4));
                #pragma unroll
                for (int o2 = 0; o2 < 8; o2++) {
                    ulonglong2 wv = wr[o2];            // LDS.128 broadcast: 2 outputs
                    ffma2(a0[2*o2],   wv.x, x01);
                    ffma2(a1[2*o2],   wv.x, x23);
                    ffma2(a0[2*o2+1], wv.y, x01);
                    ffma2(a1[2*o2+1], wv.y, x23);
                }
            }
            #pragma unroll
            for (int o = 0; o < 16; o++) {
                float4 r;
                upk(r.x, r.y, a0[o]);
                upk(r.z, r.w, a1[o]);
                *(float4*)(ob + (size_t)(half*64 + ot*16 + o)*HWN) = r;
            }
        }
        __syncthreads();
    }
}

// ======== depthwise 3x3, shuffle edges, 8 px/thread, rolling rows ========
struct Row8 {
    float4 A, B;
    float pw, nx;
};
__device__ __forceinline__ Row8 load_row8(const float* plane, int y, int lane) {
    Row8 r;
    if (y < 0 || y >= HH) {
        r.A = make_float4(0.f,0.f,0.f,0.f);
        r.B = r.A; r.pw = 0.f; r.nx = 0.f;
        float pw = __shfl_up_sync(0xffffffffu, 0.f, 1);
        float nx = __shfl_down_sync(0xffffffffu, 0.f, 1);
        (void)pw; (void)nx;
        return r;
    }
    const float* p = plane + (y << 8) + (lane << 3);
    r.A = *(const float4*)p;
    r.B = *(const float4*)(p + 4);
    float pw = __shfl_up_sync(0xffffffffu, r.B.w, 1);
    float nx = __shfl_down_sync(0xffffffffu, r.A.x, 1);
    r.pw = (lane == 0)  ? 0.f : pw;
    r.nx = (lane == 31) ? 0.f : nx;
    return r;
}
__device__ __forceinline__ void acc_row8(float* acc, const Row8& r, float wa, float wb, float wc) {
    acc[0] += wa*r.pw  + wb*r.A.x + wc*r.A.y;
    acc[1] += wa*r.A.x + wb*r.A.y + wc*r.A.z;
    acc[2] += wa*r.A.y + wb*r.A.z + wc*r.A.w;
    acc[3] += wa*r.A.z + wb*r.A.w + wc*r.B.x;
    acc[4] += wa*r.A.w + wb*r.B.x + wc*r.B.y;
    acc[5] += wa*r.B.x + wb*r.B.y + wc*r.B.z;
    acc[6] += wa*r.B.y + wb*r.B.z + wc*r.B.w;
    acc[7] += wa*r.B.z + wb*r.B.w + wc*r.nx;
}

// grid: (4 strips of 64 rows, 512 planes). warp handles 8 rows.
__global__ __launch_bounds__(256) void dw3_k(const float* __restrict__ in,
                                             const float* __restrict__ wt,
                                             float* __restrict__ out) {
    int bc = blockIdx.y;
    int c  = bc & 127;
    int warp = threadIdx.x >> 5, lane = threadIdx.x & 31;
    int yb = blockIdx.x*64 + warp*8;

    float w[9];
    #pragma unroll
    for (int k = 0; k < 9; k++) w[k] = wt[c*9 + k];

    const float* plane = in  + ((size_t)bc << 16);
    float*      oplane = out + ((size_t)bc << 16);

    Row8 rp = load_row8(plane, yb - 1, lane);
    Row8 rc = load_row8(plane, yb,     lane);
    #pragma unroll
    for (int i = 0; i < 8; i++) {
        Row8 rn = load_row8(plane, yb + i + 1, lane);
        float acc[8];
        #pragma unroll
        for (int k = 0; k < 8; k++) acc[k] = 0.f;
        acc_row8(acc, rp, w[0], w[1], w[2]);
        acc_row8(acc, rc, w[3], w[4], w[5]);
        acc_row8(acc, rn, w[6], w[7], w[8]);
        float* op = oplane + ((yb + i) << 8) + (lane << 3);
        *(float4*)op       = make_float4(acc[0], acc[1], acc[2], acc[3]);
        *(float4*)(op + 4) = make_float4(acc[4], acc[5], acc[6], acc[7]);
        rp = rc; rc = rn;
    }
}

// ---------- fused Gram reduction: q read once, both modalities ----------
__global__ __launch_bounds__(256, 1) void reduce_qk2_k(const float* __restrict__ q,
                                                       const float* __restrict__ kvr,
                                                       const float* __restrict__ kvd) {
    int chunk = blockIdx.x;
    int bh    = blockIdx.y;
    int b = bh >> 3, h = bh & 7;
    size_t qoff = ((size_t)b*64  + h*8)*HWN;
    size_t koff = ((size_t)b*128 + h*8)*HWN;

    float accr[64], accd[64], qn[8], knr[8], knd[8];
    #pragma unroll
    for (int i = 0; i < 64; i++) { accr[i] = 0.f; accd[i] = 0.f; }
    #pragma unroll
    for (int i = 0; i < 8; i++) { qn[i] = 0.f; knr[i] = 0.f; knd[i] = 0.f; }

    const int CS4 = HWN / NCHUNK / 4;
    int start = chunk * CS4;
    for (int it = threadIdx.x; it < CS4; it += blockDim.x) {
        int idx = start + it;
        float4 qv[8];
        #pragma unroll
        for (int c = 0; c < 8; c++) {
            qv[c] = ((const float4*)(q + qoff + (size_t)c*HWN))[idx];
            qn[c] += qv[c].x*qv[c].x + qv[c].y*qv[c].y + qv[c].z*qv[c].z + qv[c].w*qv[c].w;
        }
        #pragma unroll
        for (int d = 0; d < 8; d++) {
            float4 k4 = ((const float4*)(kvr + koff + (size_t)d*HWN))[idx];
            knr[d] += k4.x*k4.x + k4.y*k4.y + k4.z*k4.z + k4.w*k4.w;
            #pragma unroll
            for (int c = 0; c < 8; c++)
                accr[d*8+c] += qv[c].x*k4.x + qv[c].y*k4.y + qv[c].z*k4.z + qv[c].w*k4.w;
        }
        #pragma unroll
        for (int d = 0; d < 8; d++) {
            float4 k4 = ((const float4*)(kvd + koff + (size_t)d*HWN))[idx];
            knd[d] += k4.x*k4.x + k4.y*k4.y + k4.z*k4.z + k4.w*k4.w;
            #pragma unroll
            for (int c = 0; c < 8; c++)
                accd[d*8+c] += qv[c].x*k4.x + qv[c].y*k4.y + qv[c].z*k4.z + qv[c].w*k4.w;
        }
    }

    __shared__ float sm[8][152];
    int lane = threadIdx.x & 31, warp = threadIdx.x >> 5;
    #pragma unroll
    for (int v = 0; v < 64; v++) {
        float r = accr[v];
        for (int s = 16; s > 0; s >>= 1) r += __shfl_down_sync(0xffffffffu, r, s);
        if (lane == 0) sm[warp][v] = r;
        float r2 = accd[v];
        for (int s = 16; s > 0; s >>= 1) r2 += __shfl_down_sync(0xffffffffu, r2, s);
        if (lane == 0) sm[warp][80+v] = r2;
    }
    #pragma unroll
    for (int v = 0; v < 8; v++) {
        float r = qn[v];
        for (int s = 16; s > 0; s >>= 1) r += __shfl_down_sync(0xffffffffu, r, s);
        if (lane == 0) sm[warp][64+v] = r;
        float r2 = knr[v];
        for (int s = 16; s > 0; s >>= 1) r2 += __shfl_down_sync(0xffffffffu, r2, s);
        if (lane == 0) sm[warp][72+v] = r2;
        float r3 = knd[v];
        for (int s = 16; s > 0; s >>= 1) r3 += __shfl_down_sync(0xffffffffu, r3, s);
        if (lane == 0) sm[warp][144+v] = r3;
    }
    __syncthreads();
    if (threadIdx.x < 160) {
        int which = threadIdx.x / 80;
        int t = threadIdx.x - which*80;
        int col;
        if (which == 0) col = t;
        else            col = (t < 64) ? 80 + t : (t < 72 ? t : 72 + t);
        float s = 0.f;
        #pragma unroll
        for (int wg = 0; wg < 8; wg++) s += sm[wg][col];
        g_part[which][bh][chunk][t] = s;
    }
}

// ---------------- finish reduction + softmax ----------------
__global__ void attn_k(const float* __restrict__ temp) {
    int which = blockIdx.x >> 5;
    int bh    = blockIdx.x & 31;
    int h     = bh & 7;
    __shared__ float sm[80];
    if (threadIdx.x < 80) {
        float s = 0.f;
        #pragma unroll
        for (int ch = 0; ch < NCHUNK; ch++) s += g_part[which][bh][ch][threadIdx.x];
        sm[threadIdx.x] = s;
    }
    __syncthreads();
    if (threadIdx.x < 8) {
        int c = threadIdx.x;
        float t  = temp[h];
        float nq = fmaxf(sqrtf(sm[64+c]), 1e-12f);
        float srow[8];
        #pragma unroll
        for (int d = 0; d < 8; d++) {
            float nk = fmaxf(sqrtf(sm[72+d]), 1e-12f);
            float s = sm[d*8+c] / nk;
            if (which == 0) s /= nq;
            srow[d] = s * t;
        }
        float mx = srow[0];
        #pragma unroll
        for (int d = 1; d < 8; d++) mx = fmaxf(mx, srow[d]);
        float sum = 0.f;
        #pragma unroll
        for (int d = 0; d < 8; d++) { srow[d] = __expf(srow[d]-mx); sum += srow[d]; }
        float inv = 1.f / sum;
        #pragma unroll
        for (int d = 0; d < 8; d++) g_attn[which][bh][c*8+d] = srow[d]*inv;
    }
}

// ---------------- fused epilogue (f32x2, 2 px/thread, LDS.128 pairs) ----------------
__global__ __launch_bounds__(256) void final_k(const float* __restrict__ wproj,
                                               float* __restrict__ out) {
    __shared__ ull sA1t[512], sA2t[512];   // transposed [h][d][c], packed
    __shared__ ull sW[4096];               // [o][c] packed, c contiguous
    int b = blockIdx.y;
    for (int i = threadIdx.x; i < 512; i += 256) {
        int h = i >> 6, d = (i >> 3) & 7, c = i & 7;
        float a1 = g_attn[0][b*8 + h][c*8 + d];
        float a2 = g_attn[1][b*8 + h][c*8 + d];
        sA1t[i] = pk(a1, a1);
        sA2t[i] = pk(a2, a2);
    }
    for (int i = threadIdx.x; i < 4096; i += 256) {
        float wv = wproj[i];
        sW[i] = pk(wv, wv);
    }
    __syncthreads();

    int n = (blockIdx.x*256 + threadIdx.x)*2;
    const float* vr = g_kvr + ((size_t)b*128 + 64)*HWN + n;
    const float* vd = g_kvd + ((size_t)b*128 + 64)*HWN + n;

    ull p[64];
    #pragma unroll 1
    for (int h = 0; h < 8; h++) {
        ull os[8], oc[8];
        #pragma unroll
        for (int c = 0; c < 8; c++) { os[c] = 0ULL; oc[c] = 0ULL; }
        #pragma unroll
        for (int d = 0; d < 8; d++) {
            float2 r2 = *(const float2*)(vr + (size_t)(h*8+d)*HWN);
            float2 d2 = *(const float2*)(vd + (size_t)(h*8+d)*HWN);
            ull rr = pk(r2.x, r2.y);
            ull dd = pk(d2.x, d2.y);
            const ulonglong2* a1p = (const ulonglong2*)(sA1t + h*64 + d*8);
            const ulonglong2* a2p = (const ulonglong2*)(sA2t + h*64 + d*8);
            #pragma unroll
            for (int c2 = 0; c2 < 4; c2++) {
                ulonglong2 w1 = a1p[c2];               // LDS.128: attn1 for c=2*c2, 2*c2+1
                ffma2(os[2*c2],   w1.x, rr);
                ffma2(os[2*c2+1], w1.y, rr);
                ulonglong2 w2 = a2p[c2];
                ffma2(oc[2*c2],   w2.x, dd);
                ffma2(oc[2*c2+1], w2.y, dd);
            }
        }
        #pragma unroll
        for (int c = 0; c < 8; c++) p[h*8+c] = fmul2(os[c], oc[c]);
    }

    float* ob = out + (size_t)b*64*HWN + n;
    #pragma unroll 4
    for (int o = 0; o < 64; o++) {
        ull acc = 0ULL;
        const ulonglong2* wr = (const ulonglong2*)(sW + o*64);
        #pragma unroll
        for (int c2 = 0; c2 < 32; c2++) {
            ulonglong2 wv = wr[c2];                    // LDS.128: wproj for c=2*c2, 2*c2+1
            ffma2(acc, wv.x, p[2*c2]);
            ffma2(acc, wv.y, p[2*c2+1]);
        }
        float2 r; upk(r.x, r.y, acc);
        *(float2*)(ob + (size_t)o*HWN) = r;
    }
}

// ---------------- host launch ----------------
extern "C" void kernel_launch(void* const* d_in, const int* in_sizes, int n_in,
                              void* d_out, int out_size) {
    const float* rgb   = (const float*)d_in[0];
    const float* depth = (const float*)d_in[1];
    const float* temp  = (const float*)d_in[2];
    const float* wqr   = (const float*)d_in[3];
    const float* wqd   = (const float*)d_in[4];
    const float* wqc   = (const float*)d_in[5];
    const float* w1    = (const float*)d_in[6];
    const float* w5    = (const float*)d_in[7];
    const float* w7    = (const float*)d_in[8];
    const float* w9    = (const float*)d_in[9];
    const float* wproj = (const float*)d_in[10];
    float* out = (float*)d_out;

    void* p;
    cudaGetSymbolAddress(&p, g_qrgb); float* qrg  = (float*)p;
    cudaGetSymbolAddress(&p, g_cvt0); float* cvt0 = (float*)p;
    cudaGetSymbolAddress(&p, g_cvt1); float* cvt1 = (float*)p;
    cudaGetSymbolAddress(&p, g_kvr);  float* kvr  = (float*)p;
    cudaGetSymbolAddress(&p, g_kvd);  float* kvd  = (float*)p;

    // init-once side streams + events (host objects only; no device work here)
    static cudaStream_t s1 = 0, s2 = 0;
    static cudaEvent_t evFork1 = 0, evFork2 = 0, evMfe = 0, evDep = 0;
    if (!s1) {
        cudaStreamCreateWithFlags(&s1, cudaStreamNonBlocking);
        cudaStreamCreateWithFlags(&s2, cudaStreamNonBlocking);
        cudaEventCreateWithFlags(&evFork1, cudaEventDisableTiming);
        cudaEventCreateWithFlags(&evFork2, cudaEventDisableTiming);
        cudaEventCreateWithFlags(&evMfe,  cudaEventDisableTiming);
        cudaEventCreateWithFlags(&evDep,  cudaEventDisableTiming);
    }

    const int T = 256;
    const int MFE_BACK_SMEM = (10400 + 9360) * 4;   // 79040 B
    cudaFuncSetAttribute(mfe_back_k, cudaFuncAttributeMaxDynamicSharedMemorySize, MFE_BACK_SMEM);

    // fork: main(0) -> s1 (mfe), s2 (depth chain)
    cudaEventRecord(evFork1, 0);
    cudaStreamWaitEvent(s1, evFork1, 0);
    cudaEventRecord(evFork2, 0);
    cudaStreamWaitEvent(s2, evFork2, 0);

    // ---- branch s1: MFE ----
    dim3 fgk(9, BB*CC);
    mfe_front_k<<<fgk, T, 0, s1>>>(rgb);
    dim3 bgk(8, BB*CC);
    mfe_back_k<<<bgk, T, MFE_BACK_SMEM, s1>>>(w1, w5, w7, w9);
    cudaEventRecord(evMfe, s1);

    // ---- branch s2: depth conv -> dw3 ----
    dim3 cg(HWN/(T*4), BB);
    dim3 dg(4, BB*128);
    conv1x1_k<<<cg, T, 0, s2>>>(depth, wqd, cvt1);
    dw3_k<<<dg, T, 0, s2>>>(cvt1, wqc, kvd);
    cudaEventRecord(evDep, s2);

    // ---- main stream: rgb conv -> dw3 ----
    conv1x1_k<<<cg, T>>>(rgb, wqr, cvt0);
    dw3_k<<<dg, T>>>(cvt0, wqc, kvr);

    // join both branches into main stream
    cudaStreamWaitEvent(0, evMfe, 0);
    cudaStreamWaitEvent(0, evDep, 0);

    // ---- attention statistics ----
    dim3 rg(NCHUNK, 32);
    reduce_qk2_k<<<rg, T>>>(qrg, kvr, kvd);
    attn_k<<<64, 128>>>(temp);

    // ---- fused epilogue ----
    dim3 fg(HWN/(T*2), BB);
    final_k<<<fg, T>>>(wproj, out);
}